// round 11
// baseline (speedup 1.0000x reference)
#include <cuda_runtime.h>
#include <cuda_bf16.h>
#include <math.h>
#include <stdint.h>

// ---------------- problem constants (fixed shapes) ----------------
#define BATCH 8
#define C     64
#define HH    64
#define WW    64
#define HW    4096          // 64*64
#define HEADS 4
#define DK    32
#define HD    128           // HEADS*DK
#define KHW   1024          // 32*32 (stride-2 output)
#define THETA 0.5f
#define EPS_LN 1e-5f
#define NTOT  (BATCH*C*HW)  // 2097152
#define QK_SCALE 0.17677669529663687f  // 1/sqrt(32)

typedef unsigned long long ull;

// packed fp32x2 helpers
__device__ __forceinline__ void fma2(ull& d, ull a, ull b, ull c) {
    asm("fma.rn.f32x2 %0, %1, %2, %3;" : "=l"(d) : "l"(a), "l"(b), "l"(c));
}
__device__ __forceinline__ ull pack2(float lo, float hi) {
    ull r; asm("mov.b64 %0, {%1, %2};" : "=l"(r) : "f"(lo), "f"(hi)); return r;
}
__device__ __forceinline__ void unpack2(float& lo, float& hi, ull v) {
    asm("mov.b64 {%0, %1}, %2;" : "=f"(lo), "=f"(hi) : "l"(v));
}
__device__ __forceinline__ uint32_t bf16x2_of(float a, float b) {
    uint32_t r;
    asm("cvt.rn.satfinite.bf16x2.f32 %0, %1, %2;" : "=r"(r) : "f"(b), "f"(a));
    return r;   // lo=a, hi=b
}

// warp mma: D(16x8,f32) += A(16x16,bf16,row) * B(16x8,bf16,col)
__device__ __forceinline__ void mma_bf16(float* d, const uint32_t* a,
                                         uint32_t b0, uint32_t b1) {
    asm volatile("mma.sync.aligned.m16n8k16.row.col.f32.bf16.bf16.f32 "
        "{%0,%1,%2,%3}, {%4,%5,%6,%7}, {%8,%9}, {%0,%1,%2,%3};"
        : "+f"(d[0]), "+f"(d[1]), "+f"(d[2]), "+f"(d[3])
        : "r"(a[0]), "r"(a[1]), "r"(a[2]), "r"(a[3]), "r"(b0), "r"(b1));
}

// ldmatrix x4 (LDSM)
__device__ __forceinline__ void ldsm_x4(uint32_t& r0, uint32_t& r1,
                                        uint32_t& r2, uint32_t& r3, uint32_t addr) {
    asm volatile("ldmatrix.sync.aligned.m8n8.x4.shared.b16 {%0,%1,%2,%3}, [%4];"
        : "=r"(r0), "=r"(r1), "=r"(r2), "=r"(r3) : "r"(addr));
}

// ---------------- device scratch (static, allowed) ----------------
__device__ float  g_part_s[512];
__device__ float  g_part_s2[512];
__device__ float  g_stats[2];
__device__ float  g_weffk[512*128];
__device__ float  g_weffv[512*128];
__device__ __nv_bfloat16 g_qh[BATCH*HEADS*HW*DK];   // pre-scaled Q, bf16, [bh][q][d]
__device__ __nv_bfloat16 g_kh[BATCH*HEADS*KHW*DK];  // K bf16 [bh][key][d]
__device__ __nv_bfloat16 g_vT[BATCH*HEADS*DK*KHW];  // V bf16 transposed [bh][d][key]
__device__ float  g_ctx[BATCH*HW*HD];

// ---------------- launch 0: per-block partial sums (deterministic) ----------------
__global__ void k_part(const float* __restrict__ x)
{
    float s = 0.f, s2 = 0.f;
    int base = blockIdx.x * (NTOT/512);
    for (int i = threadIdx.x; i < NTOT/512; i += 256) {
        float v = x[base + i];
        s  += v;
        s2  = fmaf(v, v, s2);
    }
    #pragma unroll
    for (int off = 16; off; off >>= 1) {
        s  += __shfl_down_sync(0xffffffffu, s,  off);
        s2 += __shfl_down_sync(0xffffffffu, s2, off);
    }
    __shared__ float sh[2][8];
    int lane = threadIdx.x & 31, w = threadIdx.x >> 5;
    if (lane == 0) { sh[0][w] = s; sh[1][w] = s2; }
    __syncthreads();
    if (threadIdx.x == 0) {
        float ts = 0.f, ts2 = 0.f;
        for (int i = 0; i < 8; i++) { ts += sh[0][i]; ts2 += sh[1][i]; }
        g_part_s[blockIdx.x]  = ts;
        g_part_s2[blockIdx.x] = ts2;
    }
}

// ---------------- launch 1: stats finalize (block 0) + weff fold (blocks 1..256) ----------------
__global__ void k_stats_weff(const float* __restrict__ fck_w, const float* __restrict__ wk,
                             const float* __restrict__ fcv_w, const float* __restrict__ wv)
{
    if (blockIdx.x == 0) {
        __shared__ double sh[512], sh2[512];
        int t = threadIdx.x;
        sh[t]  = (double)g_part_s[t];
        sh2[t] = (double)g_part_s2[t];
        __syncthreads();
        for (int o = 256; o; o >>= 1) {
            if (t < o) { sh[t] += sh[t+o]; sh2[t] += sh2[t+o]; }
            __syncthreads();
        }
        if (t == 0) {
            double n = (double)NTOT;
            double m = sh[0] / n;
            double var = sh2[0] / n - m*m;
            g_stats[0] = (float)m;
            g_stats[1] = (float)rsqrt(var + (double)EPS_LN);
        }
        return;
    }
    int b2 = blockIdx.x - 1;          // 0..255
    int f  = b2 & 127;
    const float* fw = (b2 >> 7) ? fcv_w : fck_w;
    const float* w8 = (b2 >> 7) ? wv    : wk;
    float*      out = (b2 >> 7) ? g_weffv : g_weffk;
    int idx = threadIdx.x;            // 0..511
    float acc = 0.f;
    #pragma unroll 16
    for (int co = 0; co < 64; co++)
        acc = fmaf(__ldg(&fw[f*64+co]), w8[co*512+idx], acc);
    out[idx*128+f] = acc;
}

// ---------------- launch 2: merged Q projection + PDC-conv K/V projection (bf16 out) ----------------
// 256 threads. blockIdx.x < 128: qproj tile (32 positions); else kv tile (32 positions).
__global__ void __launch_bounds__(256) k_qkv(const float* __restrict__ x,
                    const float* __restrict__ fcq_w, const float* __restrict__ fcq_b,
                    const float* __restrict__ fck_b, const float* __restrict__ fcv_b)
{
    extern __shared__ float sm[];     // 64 KB dynamic
    int b   = blockIdx.y;
    int tid = threadIdx.x;

    if (blockIdx.x < 128) {
        // ---- Q projection: 32 positions, thread = (f, pos-half) ----
        float* xs = sm;               // [c][pos], 64*32
        float* ws = sm + 2048;        // [c][f] padded 129
        int p0 = blockIdx.x * 32;
        float mean = g_stats[0], rstd = g_stats[1];

        for (int e = tid; e < 8192; e += 256) {
            int f = e >> 6, c = e & 63;
            ws[c*129+f] = fcq_w[e];
        }
        const float* xb = x + (size_t)b*C*HW;
        for (int e = tid; e < 2048; e += 256) {
            int c = e >> 5, pos = e & 31;
            xs[c*32+pos] = (xb[c*HW + p0 + pos] - mean) * rstd;
        }
        __syncthreads();

        int f  = tid & 127;
        int ph = tid >> 7;            // position half: 0 -> 0..15, 1 -> 16..31
        float bias = fcq_b[f];
        ull acc2[8];
        #pragma unroll
        for (int i = 0; i < 8; i++) acc2[i] = pack2(bias, bias);
        for (int c = 0; c < 64; c++) {
            float w_ = ws[c*129+f];
            ull w2 = pack2(w_, w_);
            const ull* xr = (const ull*)(xs + c*32 + ph*16);
            #pragma unroll
            for (int i = 0; i < 8; i++) fma2(acc2[i], w2, xr[i], acc2[i]);
        }
        int h = f >> 5, d = f & 31;
        __nv_bfloat16* qb = g_qh + ((size_t)(b*HEADS+h)*HW + p0 + ph*16)*DK + d;
        #pragma unroll
        for (int i = 0; i < 8; i++) {
            float a0, a1; unpack2(a0, a1, acc2[i]);
            qb[(size_t)(2*i)*DK]   = __float2bfloat16(a0 * QK_SCALE);
            qb[(size_t)(2*i+1)*DK] = __float2bfloat16(a1 * QK_SCALE);
        }
    } else {
        // ---- PDC conv gather + K/V projection: 32 positions, thread = (f, K-or-V) ----
        float* gs = sm;               // [idx][pos] : 512*32 = 16384 floats
        int p0 = (blockIdx.x - 128) * 32;
        const float* xb = x + (size_t)b*C*HW;

        for (int e = tid; e < 16384; e += 256) {
            int idx = e >> 5;
            int pos = e & 31;
            int ci = idx >> 3, t = idx & 7;
            int pg = p0 + pos;
            int i = pg >> 5, j = pg & 31;
            int cy = i*2, cx = j*2;
            int k9 = (t < 4) ? t : t + 1;      // skip 3x3 center
            int ny = cy + (k9/3) - 1;
            int nx = cx + (k9%3) - 1;
            float ctr = xb[ci*HW + cy*WW + cx];
            float nb = 0.f;
            if (ny >= 0 && ny < HH && nx >= 0 && nx < WW)
                nb = xb[ci*HW + ny*WW + nx];
            gs[idx*32+pos] = nb - THETA*ctr;
        }
        __syncthreads();

        int f  = tid & 127;
        int kv = tid >> 7;            // 0 -> K, 1 -> V
        const float* weff = kv ? g_weffv : g_weffk;
        float bias = kv ? fcv_b[f] : fck_b[f];
        ull acc2[16];
        #pragma unroll
        for (int i = 0; i < 16; i++) acc2[i] = pack2(bias, bias);
        #pragma unroll 2
        for (int idx = 0; idx < 512; idx++) {
            float w_ = weff[idx*128+f];
            ull w2 = pack2(w_, w_);
            const ull* gr = (const ull*)(gs + idx*32);
            #pragma unroll
            for (int i = 0; i < 16; i++) fma2(acc2[i], w2, gr[i], acc2[i]);
        }
        int h = f >> 5, d = f & 31;
        if (kv == 0) {
            __nv_bfloat16* kb = g_kh + ((size_t)(b*HEADS+h)*KHW + p0)*DK + d;
            #pragma unroll
            for (int i = 0; i < 16; i++) {
                float a0, a1; unpack2(a0, a1, acc2[i]);
                kb[(size_t)(2*i)*DK]   = __float2bfloat16(a0);
                kb[(size_t)(2*i+1)*DK] = __float2bfloat16(a1);
            }
        } else {
            uint32_t* vb = (uint32_t*)(g_vT + ((size_t)(b*HEADS+h)*DK + d)*KHW + p0);
            #pragma unroll
            for (int i = 0; i < 16; i++) {
                float a0, a1; unpack2(a0, a1, acc2[i]);
                vb[i] = bf16x2_of(a0, a1);
            }
        }
    }
}

// ---------------- launch 3: attention via mma.sync + ldmatrix ----------------
// CTA: 64 q-rows x one (b,h). 4 warps, warp w owns 16 rows. 5 CTAs/SM.
#define KT 64
__global__ void __launch_bounds__(128, 5) k_attn(const float* __restrict__ Bmat)
{
    __shared__ __align__(16) __nv_bfloat16 Ksm[KT][40];     // keys x dims (stride 80B)
    __shared__ __align__(16) __nv_bfloat16 Vsm[DK][KT+8];   // dims x keys (stride 144B)
    int tid = threadIdx.x;
    int w = tid >> 5, l = tid & 31;
    int g = l >> 2, t = l & 3;
    int bh = blockIdx.y, h = bh & 3;
    int q0 = blockIdx.x * 64 + w * 16;

    // Q a-frags (once): [kchunk][4] for this warp's 16 rows
    uint32_t qa[2][4];
    const __nv_bfloat16* Qb = g_qh + ((size_t)bh*HW + q0)*DK;
    #pragma unroll
    for (int kc = 0; kc < 2; kc++) {
        qa[kc][0] = *(const uint32_t*)(Qb + (size_t)g*DK     + kc*16 + 2*t);
        qa[kc][1] = *(const uint32_t*)(Qb + (size_t)(g+8)*DK + kc*16 + 2*t);
        qa[kc][2] = *(const uint32_t*)(Qb + (size_t)g*DK     + kc*16 + 8 + 2*t);
        qa[kc][3] = *(const uint32_t*)(Qb + (size_t)(g+8)*DK + kc*16 + 8 + 2*t);
    }

    float o[4][4];                    // [dim-block][frag]
    float lsum[2];                    // rows g / g+8
    lsum[0] = lsum[1] = 0.f;
    #pragma unroll
    for (int db = 0; db < 4; db++)
        o[db][0] = o[db][1] = o[db][2] = o[db][3] = 0.f;

    // per-lane ldmatrix base addresses
    uint32_t ksm0 = (uint32_t)__cvta_generic_to_shared(&Ksm[0][0]);
    uint32_t vsm0 = (uint32_t)__cvta_generic_to_shared(&Vsm[0][0]);
    uint32_t k_lane = ksm0 + (uint32_t)((l & 7)*80 + (l >> 3)*16);
    uint32_t v_lane = vsm0 + (uint32_t)(((l >> 4)*8 + (l & 7))*144 + ((l >> 3) & 1)*16);

    const float* Bb = Bmat + (size_t)h*HW*KHW;
    const uint4* kg4 = (const uint4*)(g_kh + (size_t)bh*KHW*DK);   // 4 uint4 per key
    const uint4* vg4 = (const uint4*)(g_vT + (size_t)bh*DK*KHW);   // 128 uint4 per dim

    for (int c0 = 0; c0 < KHW; c0 += KT) {
        __syncthreads();
        // K tile: 256 uint4 chunks (64 keys x 64B)
        #pragma unroll
        for (int i = 0; i < 2; i++) {
            int e = tid + i*128;
            int r = e >> 2, c = e & 3;
            *(uint4*)((char*)&Ksm[0][0] + r*80 + c*16) = kg4[(size_t)(c0 + r)*4 + c];
        }
        // V tile: 256 uint4 chunks (32 dims x 128B)
        #pragma unroll
        for (int i = 0; i < 2; i++) {
            int e = tid + i*128;
            int d = e >> 3, c = e & 7;
            *(uint4*)((char*)&Vsm[0][0] + d*144 + c*16) = vg4[(size_t)d*128 + (c0 >> 3) + c];
        }
        __syncthreads();

        #pragma unroll
        for (int half = 0; half < 2; half++) {
            int c32 = half * 32;
            // ---- S = Q K^T over 32 keys (ldmatrix b-frags) ----
            float s[4][4];
            #pragma unroll
            for (int nb = 0; nb < 4; nb++)
                s[nb][0] = s[nb][1] = s[nb][2] = s[nb][3] = 0.f;
            #pragma unroll
            for (int nb = 0; nb < 4; nb++) {
                uint32_t b0, b1, b2, b3;
                ldsm_x4(b0, b1, b2, b3, k_lane + (uint32_t)((c32 + 8*nb)*80));
                mma_bf16(s[nb], qa[0], b0, b1);
                mma_bf16(s[nb], qa[1], b2, b3);
            }
            // ---- epilogue: +bias, exp, l, pack P ----
            uint32_t pa[2][4];
            #pragma unroll
            for (int nb = 0; nb < 4; nb++) {
                int row = q0 + g;
                size_t bidx = (size_t)row*KHW + c0 + c32 + 8*nb + 2*t;
                float2 bv0 = *(const float2*)(Bb + bidx);
                float2 bv1 = *(const float2*)(Bb + bidx + (size_t)8*KHW);
                float p0 = __expf(s[nb][0] + bv0.x);
                float p1 = __expf(s[nb][1] + bv0.y);
                float p2 = __expf(s[nb][2] + bv1.x);
                float p3 = __expf(s[nb][3] + bv1.y);
                lsum[0] += (p0 + p1);
                lsum[1] += (p2 + p3);
                int u = nb >> 1, odd = nb & 1;
                pa[u][2*odd]     = bf16x2_of(p0, p1);
                pa[u][2*odd + 1] = bf16x2_of(p2, p3);
            }
            // ---- O += P V (ldmatrix b-frags, 2 dim-blocks per x4) ----
            #pragma unroll
            for (int u = 0; u < 2; u++)
                #pragma unroll
                for (int dp = 0; dp < 2; dp++) {
                    uint32_t b0, b1, b2, b3;
                    ldsm_x4(b0, b1, b2, b3,
                            v_lane + (uint32_t)(dp*2304 + (c32 + 16*u)*2));
                    mma_bf16(o[2*dp],     pa[u], b0, b1);
                    mma_bf16(o[2*dp + 1], pa[u], b2, b3);
                }
        }
    }

    // reduce l over the t-quad, normalize, store ctx
    #pragma unroll
    for (int r = 0; r < 2; r++) {
        float v = lsum[r];
        v += __shfl_xor_sync(0xffffffffu, v, 1);
        v += __shfl_xor_sync(0xffffffffu, v, 2);
        lsum[r] = 1.f / v;
    }
    int b = bh >> 2;
    int row = q0 + g;
    #pragma unroll
    for (int db = 0; db < 4; db++) {
        int dim = h*DK + 8*db + 2*t;
        float2 lo = make_float2(o[db][0]*lsum[0], o[db][1]*lsum[0]);
        float2 hi = make_float2(o[db][2]*lsum[1], o[db][3]*lsum[1]);
        *(float2*)(g_ctx + ((size_t)b*HW + row)*HD + dim)     = lo;
        *(float2*)(g_ctx + ((size_t)b*HW + row + 8)*HD + dim) = hi;
    }
}

// ---------------- launch 4: output projection + residual, f32x2 packed ----------------
__global__ void k_out(const float* __restrict__ x,
                      const float* __restrict__ fco_w,
                      const float* __restrict__ fco_b,
                      float* __restrict__ out)
{
    __shared__ float cs[16*128];
    __shared__ float ws2[64*130];
    int b   = blockIdx.y;
    int p0  = blockIdx.x * 16;
    int tid = threadIdx.x;

    for (int e = tid; e < 8192; e += 256) {
        int ch = e >> 7, k = e & 127;
        ws2[ch*130+k] = fco_w[e];
    }
    const float* ctx = g_ctx + ((size_t)b*HW + p0)*HD;
    for (int e = tid; e < 2048; e += 256) cs[e] = ctx[e];
    __syncthreads();

    int ch = tid & 63;
    int pg = tid >> 6;
    ull acc2[4];
    #pragma unroll
    for (int pi = 0; pi < 4; pi++) acc2[pi] = 0ull;
    const ull* wr = (const ull*)(ws2 + ch*130);
    #pragma unroll 4
    for (int kp = 0; kp < 64; kp++) {
        ull w2 = wr[kp];
        #pragma unroll
        for (int pi = 0; pi < 4; pi++) {
            ull c2 = *(const ull*)(cs + (pg*4+pi)*128 + 2*kp);
            fma2(acc2[pi], w2, c2, acc2[pi]);
        }
    }
    float bias = fco_b[ch];
    #pragma unroll
    for (int pi = 0; pi < 4; pi++) {
        float a0, a1; unpack2(a0, a1, acc2[pi]);
        int pos = pg*4 + pi;
        size_t oi = (size_t)b*(C*HW) + (size_t)(p0+pos)*64 + ch;
        out[oi] = (a0 + a1) + bias + x[oi];
    }
}

// ---------------- launcher (5 launches; k_attn is launch idx 3) ----------------
extern "C" void kernel_launch(void* const* d_in, const int* in_sizes, int n_in,
                              void* d_out, int out_size)
{
    (void)n_in; (void)out_size; (void)in_sizes;
    const float* x      = (const float*)d_in[0];
    const float* wk     = (const float*)d_in[1];
    const float* wv     = (const float*)d_in[2];
    const float* fcq_w  = (const float*)d_in[3];
    const float* fcq_b  = (const float*)d_in[4];
    const float* fck_w  = (const float*)d_in[5];
    const float* fck_b  = (const float*)d_in[6];
    const float* fcv_w  = (const float*)d_in[7];
    const float* fcv_b  = (const float*)d_in[8];
    const float* fco_w  = (const float*)d_in[9];
    const float* fco_b  = (const float*)d_in[10];
    const float* Bmat   = (const float*)d_in[11];
    float* out = (float*)d_out;

    cudaFuncSetAttribute(k_qkv, cudaFuncAttributeMaxDynamicSharedMemorySize, 65536);

    k_part<<<512, 256>>>(x);
    k_stats_weff<<<257, 512>>>(fck_w, wk, fcv_w, wv);
    k_qkv<<<dim3(128+32, BATCH), 256, 65536>>>(x, fcq_w, fcq_b, fck_b, fcv_b);
    k_attn<<<dim3(HW/64, BATCH*HEADS), 128>>>(Bmat);
    k_out<<<dim3(HW/16, BATCH), 256>>>(x, fco_w, fco_b, out);
}

// round 12
// speedup vs baseline: 1.1830x; 1.1830x over previous
#include <cuda_runtime.h>
#include <cuda_bf16.h>
#include <math.h>
#include <stdint.h>

// ---------------- problem constants (fixed shapes) ----------------
#define BATCH 8
#define C     64
#define HH    64
#define WW    64
#define HW    4096          // 64*64
#define HEADS 4
#define DK    32
#define HD    128           // HEADS*DK
#define KHW   1024          // 32*32 (stride-2 output)
#define THETA 0.5f
#define EPS_LN 1e-5f
#define NTOT  (BATCH*C*HW)  // 2097152
#define QK_SCALE 0.17677669529663687f  // 1/sqrt(32)

typedef unsigned long long ull;

// packed fp32x2 helpers
__device__ __forceinline__ void fma2(ull& d, ull a, ull b, ull c) {
    asm("fma.rn.f32x2 %0, %1, %2, %3;" : "=l"(d) : "l"(a), "l"(b), "l"(c));
}
__device__ __forceinline__ ull pack2(float lo, float hi) {
    ull r; asm("mov.b64 %0, {%1, %2};" : "=l"(r) : "f"(lo), "f"(hi)); return r;
}
__device__ __forceinline__ void unpack2(float& lo, float& hi, ull v) {
    asm("mov.b64 {%0, %1}, %2;" : "=f"(lo), "=f"(hi) : "l"(v));
}
__device__ __forceinline__ uint32_t bf16x2_of(float a, float b) {
    uint32_t r;
    asm("cvt.rn.satfinite.bf16x2.f32 %0, %1, %2;" : "=r"(r) : "f"(b), "f"(a));
    return r;   // lo=a, hi=b
}

// warp mma: D(16x8,f32) += A(16x16,bf16,row) * B(16x8,bf16,col)
__device__ __forceinline__ void mma_bf16(float* d, const uint32_t* a,
                                         uint32_t b0, uint32_t b1) {
    asm volatile("mma.sync.aligned.m16n8k16.row.col.f32.bf16.bf16.f32 "
        "{%0,%1,%2,%3}, {%4,%5,%6,%7}, {%8,%9}, {%0,%1,%2,%3};"
        : "+f"(d[0]), "+f"(d[1]), "+f"(d[2]), "+f"(d[3])
        : "r"(a[0]), "r"(a[1]), "r"(a[2]), "r"(a[3]), "r"(b0), "r"(b1));
}

// ldmatrix x4 (LDSM)
__device__ __forceinline__ void ldsm_x4(uint32_t& r0, uint32_t& r1,
                                        uint32_t& r2, uint32_t& r3, uint32_t addr) {
    asm volatile("ldmatrix.sync.aligned.m8n8.x4.shared.b16 {%0,%1,%2,%3}, [%4];"
        : "=r"(r0), "=r"(r1), "=r"(r2), "=r"(r3) : "r"(addr));
}

// ---------------- device scratch (static, allowed) ----------------
__device__ float  g_part_s[512];
__device__ float  g_part_s2[512];
__device__ float  g_stats[2];
__device__ float  g_weffk[512*128];
__device__ float  g_weffv[512*128];
__device__ __nv_bfloat16 g_qh[BATCH*HEADS*HW*DK];   // pre-scaled Q, bf16, [bh][q][d]
__device__ __nv_bfloat16 g_kh[BATCH*HEADS*KHW*DK];  // K bf16 [bh][key][d]
__device__ __nv_bfloat16 g_vT[BATCH*HEADS*DK*KHW];  // V bf16 transposed [bh][d][key]
__device__ float  g_ctx[BATCH*HW*HD];

// ---------------- launch 0: per-block partial sums (deterministic) ----------------
__global__ void k_part(const float* __restrict__ x)
{
    float s = 0.f, s2 = 0.f;
    int base = blockIdx.x * (NTOT/512);
    for (int i = threadIdx.x; i < NTOT/512; i += 256) {
        float v = x[base + i];
        s  += v;
        s2  = fmaf(v, v, s2);
    }
    #pragma unroll
    for (int off = 16; off; off >>= 1) {
        s  += __shfl_down_sync(0xffffffffu, s,  off);
        s2 += __shfl_down_sync(0xffffffffu, s2, off);
    }
    __shared__ float sh[2][8];
    int lane = threadIdx.x & 31, w = threadIdx.x >> 5;
    if (lane == 0) { sh[0][w] = s; sh[1][w] = s2; }
    __syncthreads();
    if (threadIdx.x == 0) {
        float ts = 0.f, ts2 = 0.f;
        for (int i = 0; i < 8; i++) { ts += sh[0][i]; ts2 += sh[1][i]; }
        g_part_s[blockIdx.x]  = ts;
        g_part_s2[blockIdx.x] = ts2;
    }
}

// ---------------- launch 1: stats finalize (block 0) + weff fold (blocks 1..256) ----------------
__global__ void k_stats_weff(const float* __restrict__ fck_w, const float* __restrict__ wk,
                             const float* __restrict__ fcv_w, const float* __restrict__ wv)
{
    if (blockIdx.x == 0) {
        __shared__ double sh[512], sh2[512];
        int t = threadIdx.x;
        sh[t]  = (double)g_part_s[t];
        sh2[t] = (double)g_part_s2[t];
        __syncthreads();
        for (int o = 256; o; o >>= 1) {
            if (t < o) { sh[t] += sh[t+o]; sh2[t] += sh2[t+o]; }
            __syncthreads();
        }
        if (t == 0) {
            double n = (double)NTOT;
            double m = sh[0] / n;
            double var = sh2[0] / n - m*m;
            g_stats[0] = (float)m;
            g_stats[1] = (float)rsqrt(var + (double)EPS_LN);
        }
        return;
    }
    int b2 = blockIdx.x - 1;          // 0..255
    int f  = b2 & 127;
    const float* fw = (b2 >> 7) ? fcv_w : fck_w;
    const float* w8 = (b2 >> 7) ? wv    : wk;
    float*      out = (b2 >> 7) ? g_weffv : g_weffk;
    int idx = threadIdx.x;            // 0..511
    float acc = 0.f;
    #pragma unroll 16
    for (int co = 0; co < 64; co++)
        acc = fmaf(__ldg(&fw[f*64+co]), w8[co*512+idx], acc);
    out[idx*128+f] = acc;
}

// ---------------- launch 2: merged Q projection + PDC-conv K/V projection (bf16 out) ----------------
__global__ void __launch_bounds__(128) k_qkv(const float* __restrict__ x,
                    const float* __restrict__ fcq_w, const float* __restrict__ fcq_b,
                    const float* __restrict__ fck_b, const float* __restrict__ fcv_b)
{
    __shared__ float sm[9280];
    int b   = blockIdx.y;
    int tid = threadIdx.x;

    if (blockIdx.x < 256) {
        float* xs = sm;               // [c][pos], 64*16
        float* ws = sm + 1024;        // [c][f] padded 129
        int p0 = blockIdx.x * 16;
        float mean = g_stats[0], rstd = g_stats[1];

        for (int e = tid; e < 8192; e += 128) {
            int f = e >> 6, c = e & 63;
            ws[c*129+f] = fcq_w[e];
        }
        const float* xb = x + (size_t)b*C*HW;
        for (int e = tid; e < 1024; e += 128) {
            int c = e >> 4, pos = e & 15;
            xs[c*16+pos] = (xb[c*HW + p0 + pos] - mean) * rstd;
        }
        __syncthreads();

        int f = tid;
        float bias = fcq_b[f];
        ull acc2[8];
        #pragma unroll
        for (int i = 0; i < 8; i++) acc2[i] = pack2(bias, bias);
        for (int c = 0; c < 64; c++) {
            float w_ = ws[c*129+f];
            ull w2 = pack2(w_, w_);
            const ull* xr = (const ull*)(xs + c*16);
            #pragma unroll
            for (int i = 0; i < 8; i++) fma2(acc2[i], w2, xr[i], acc2[i]);
        }
        int h = f >> 5, d = f & 31;
        __nv_bfloat16* qb = g_qh + ((size_t)(b*HEADS+h)*HW + p0)*DK + d;
        #pragma unroll
        for (int i = 0; i < 8; i++) {
            float a0, a1; unpack2(a0, a1, acc2[i]);
            qb[(size_t)(2*i)*DK]   = __float2bfloat16(a0 * QK_SCALE);
            qb[(size_t)(2*i+1)*DK] = __float2bfloat16(a1 * QK_SCALE);
        }
    } else {
        float* gs = sm;               // [idx][pos] : 512*16
        int p0 = (blockIdx.x - 256) * 16;
        const float* xb = x + (size_t)b*C*HW;

        for (int e = tid; e < 8192; e += 128) {
            int idx = e >> 4;
            int pos = e & 15;
            int ci = idx >> 3, t = idx & 7;
            int pg = p0 + pos;
            int i = pg >> 5, j = pg & 31;
            int cy = i*2, cx = j*2;
            int k9 = (t < 4) ? t : t + 1;      // skip 3x3 center
            int ny = cy + (k9/3) - 1;
            int nx = cx + (k9%3) - 1;
            float ctr = xb[ci*HW + cy*WW + cx];
            float nb = 0.f;
            if (ny >= 0 && ny < HH && nx >= 0 && nx < WW)
                nb = xb[ci*HW + ny*WW + nx];
            gs[idx*16+pos] = nb - THETA*ctr;
        }
        __syncthreads();

        int f = tid;
        float bk = fck_b[f], bv = fcv_b[f];
        ull ak2[8], av2[8];
        #pragma unroll
        for (int i = 0; i < 8; i++) { ak2[i] = pack2(bk, bk); av2[i] = pack2(bv, bv); }
        #pragma unroll 4
        for (int idx = 0; idx < 512; idx++) {
            float wk_ = g_weffk[idx*128+f];
            float wv_ = g_weffv[idx*128+f];
            ull wk2 = pack2(wk_, wk_);
            ull wv2 = pack2(wv_, wv_);
            const ull* gr = (const ull*)(gs + idx*16);
            #pragma unroll
            for (int i = 0; i < 8; i++) {
                ull gg = gr[i];
                fma2(ak2[i], wk2, gg, ak2[i]);
                fma2(av2[i], wv2, gg, av2[i]);
            }
        }
        int h = f >> 5, d = f & 31;
        __nv_bfloat16* kb = g_kh + ((size_t)(b*HEADS+h)*KHW + p0)*DK + d;
        uint32_t* vb = (uint32_t*)(g_vT + ((size_t)(b*HEADS+h)*DK + d)*KHW + p0);
        #pragma unroll
        for (int i = 0; i < 8; i++) {
            float k0, k1, v0, v1;
            unpack2(k0, k1, ak2[i]);
            unpack2(v0, v1, av2[i]);
            kb[(size_t)(2*i)*DK]   = __float2bfloat16(k0);
            kb[(size_t)(2*i+1)*DK] = __float2bfloat16(k1);
            vb[i] = bf16x2_of(v0, v1);   // keys p0+2i, p0+2i+1 at dim d
        }
    }
}

// ---------------- launch 3: attention via mma.sync + ldmatrix ----------------
// CTA: 64 q-rows x one (b,h). 4 warps, warp w owns 16 rows. 5 CTAs/SM.
#define KT 64
__global__ void __launch_bounds__(128, 5) k_attn(const float* __restrict__ Bmat)
{
    __shared__ __align__(16) __nv_bfloat16 Ksm[KT][40];     // keys x dims (stride 80B)
    __shared__ __align__(16) __nv_bfloat16 Vsm[DK][KT+8];   // dims x keys (stride 144B)
    int tid = threadIdx.x;
    int w = tid >> 5, l = tid & 31;
    int g = l >> 2, t = l & 3;
    int bh = blockIdx.y, h = bh & 3;
    int q0 = blockIdx.x * 64 + w * 16;

    // Q a-frags (once): [kchunk][4] for this warp's 16 rows
    uint32_t qa[2][4];
    const __nv_bfloat16* Qb = g_qh + ((size_t)bh*HW + q0)*DK;
    #pragma unroll
    for (int kc = 0; kc < 2; kc++) {
        qa[kc][0] = *(const uint32_t*)(Qb + (size_t)g*DK     + kc*16 + 2*t);
        qa[kc][1] = *(const uint32_t*)(Qb + (size_t)(g+8)*DK + kc*16 + 2*t);
        qa[kc][2] = *(const uint32_t*)(Qb + (size_t)g*DK     + kc*16 + 8 + 2*t);
        qa[kc][3] = *(const uint32_t*)(Qb + (size_t)(g+8)*DK + kc*16 + 8 + 2*t);
    }

    float o[4][4];                    // [dim-block][frag]
    float lsum[2];                    // rows g / g+8
    lsum[0] = lsum[1] = 0.f;
    #pragma unroll
    for (int db = 0; db < 4; db++)
        o[db][0] = o[db][1] = o[db][2] = o[db][3] = 0.f;

    // per-lane ldmatrix base addresses
    uint32_t ksm0 = (uint32_t)__cvta_generic_to_shared(&Ksm[0][0]);
    uint32_t vsm0 = (uint32_t)__cvta_generic_to_shared(&Vsm[0][0]);
    uint32_t k_lane = ksm0 + (uint32_t)((l & 7)*80 + (l >> 3)*16);
    uint32_t v_lane = vsm0 + (uint32_t)(((l >> 4)*8 + (l & 7))*144 + ((l >> 3) & 1)*16);

    const float* Bb = Bmat + (size_t)h*HW*KHW;
    const uint4* kg4 = (const uint4*)(g_kh + (size_t)bh*KHW*DK);   // 4 uint4 per key
    const uint4* vg4 = (const uint4*)(g_vT + (size_t)bh*DK*KHW);   // 128 uint4 per dim

    for (int c0 = 0; c0 < KHW; c0 += KT) {
        __syncthreads();
        // K tile: 256 uint4 chunks (64 keys x 64B)
        #pragma unroll
        for (int i = 0; i < 2; i++) {
            int e = tid + i*128;
            int r = e >> 2, c = e & 3;
            *(uint4*)((char*)&Ksm[0][0] + r*80 + c*16) = kg4[(size_t)(c0 + r)*4 + c];
        }
        // V tile: 256 uint4 chunks (32 dims x 128B)
        #pragma unroll
        for (int i = 0; i < 2; i++) {
            int e = tid + i*128;
            int d = e >> 3, c = e & 7;
            *(uint4*)((char*)&Vsm[0][0] + d*144 + c*16) = vg4[(size_t)d*128 + (c0 >> 3) + c];
        }
        __syncthreads();

        #pragma unroll
        for (int half = 0; half < 2; half++) {
            int c32 = half * 32;
            // ---- S = Q K^T over 32 keys (ldmatrix b-frags) ----
            float s[4][4];
            #pragma unroll
            for (int nb = 0; nb < 4; nb++)
                s[nb][0] = s[nb][1] = s[nb][2] = s[nb][3] = 0.f;
            #pragma unroll
            for (int nb = 0; nb < 4; nb++) {
                uint32_t b0, b1, b2, b3;
                ldsm_x4(b0, b1, b2, b3, k_lane + (uint32_t)((c32 + 8*nb)*80));
                mma_bf16(s[nb], qa[0], b0, b1);
                mma_bf16(s[nb], qa[1], b2, b3);
            }
            // ---- epilogue: +bias, exp, l, pack P ----
            uint32_t pa[2][4];
            #pragma unroll
            for (int nb = 0; nb < 4; nb++) {
                int row = q0 + g;
                size_t bidx = (size_t)row*KHW + c0 + c32 + 8*nb + 2*t;
                float2 bv0 = *(const float2*)(Bb + bidx);
                float2 bv1 = *(const float2*)(Bb + bidx + (size_t)8*KHW);
                float p0 = __expf(s[nb][0] + bv0.x);
                float p1 = __expf(s[nb][1] + bv0.y);
                float p2 = __expf(s[nb][2] + bv1.x);
                float p3 = __expf(s[nb][3] + bv1.y);
                lsum[0] += (p0 + p1);
                lsum[1] += (p2 + p3);
                int u = nb >> 1, odd = nb & 1;
                pa[u][2*odd]     = bf16x2_of(p0, p1);
                pa[u][2*odd + 1] = bf16x2_of(p2, p3);
            }
            // ---- O += P V (ldmatrix b-frags, 2 dim-blocks per x4) ----
            #pragma unroll
            for (int u = 0; u < 2; u++)
                #pragma unroll
                for (int dp = 0; dp < 2; dp++) {
                    uint32_t b0, b1, b2, b3;
                    ldsm_x4(b0, b1, b2, b3,
                            v_lane + (uint32_t)(dp*2304 + (c32 + 16*u)*2));
                    mma_bf16(o[2*dp],     pa[u], b0, b1);
                    mma_bf16(o[2*dp + 1], pa[u], b2, b3);
                }
        }
    }

    // reduce l over the t-quad, normalize, store ctx
    #pragma unroll
    for (int r = 0; r < 2; r++) {
        float v = lsum[r];
        v += __shfl_xor_sync(0xffffffffu, v, 1);
        v += __shfl_xor_sync(0xffffffffu, v, 2);
        lsum[r] = 1.f / v;
    }
    int b = bh >> 2;
    int row = q0 + g;
    #pragma unroll
    for (int db = 0; db < 4; db++) {
        int dim = h*DK + 8*db + 2*t;
        float2 lo = make_float2(o[db][0]*lsum[0], o[db][1]*lsum[0]);
        float2 hi = make_float2(o[db][2]*lsum[1], o[db][3]*lsum[1]);
        *(float2*)(g_ctx + ((size_t)b*HW + row)*HD + dim)     = lo;
        *(float2*)(g_ctx + ((size_t)b*HW + row + 8)*HD + dim) = hi;
    }
}

// ---------------- launch 4: output projection + residual, f32x2 packed ----------------
__global__ void k_out(const float* __restrict__ x,
                      const float* __restrict__ fco_w,
                      const float* __restrict__ fco_b,
                      float* __restrict__ out)
{
    __shared__ float cs[16*128];
    __shared__ float ws2[64*130];
    int b   = blockIdx.y;
    int p0  = blockIdx.x * 16;
    int tid = threadIdx.x;

    for (int e = tid; e < 8192; e += 256) {
        int ch = e >> 7, k = e & 127;
        ws2[ch*130+k] = fco_w[e];
    }
    const float* ctx = g_ctx + ((size_t)b*HW + p0)*HD;
    for (int e = tid; e < 2048; e += 256) cs[e] = ctx[e];
    __syncthreads();

    int ch = tid & 63;
    int pg = tid >> 6;
    ull acc2[4];
    #pragma unroll
    for (int pi = 0; pi < 4; pi++) acc2[pi] = 0ull;
    const ull* wr = (const ull*)(ws2 + ch*130);
    #pragma unroll 4
    for (int kp = 0; kp < 64; kp++) {
        ull w2 = wr[kp];
        #pragma unroll
        for (int pi = 0; pi < 4; pi++) {
            ull c2 = *(const ull*)(cs + (pg*4+pi)*128 + 2*kp);
            fma2(acc2[pi], w2, c2, acc2[pi]);
        }
    }
    float bias = fco_b[ch];
    #pragma unroll
    for (int pi = 0; pi < 4; pi++) {
        float a0, a1; unpack2(a0, a1, acc2[pi]);
        int pos = pg*4 + pi;
        size_t oi = (size_t)b*(C*HW) + (size_t)(p0+pos)*64 + ch;
        out[oi] = (a0 + a1) + bias + x[oi];
    }
}

// ---------------- launcher (5 launches; k_attn is launch idx 3) ----------------
extern "C" void kernel_launch(void* const* d_in, const int* in_sizes, int n_in,
                              void* d_out, int out_size)
{
    (void)n_in; (void)out_size; (void)in_sizes;
    const float* x      = (const float*)d_in[0];
    const float* wk     = (const float*)d_in[1];
    const float* wv     = (const float*)d_in[2];
    const float* fcq_w  = (const float*)d_in[3];
    const float* fcq_b  = (const float*)d_in[4];
    const float* fck_w  = (const float*)d_in[5];
    const float* fck_b  = (const float*)d_in[6];
    const float* fcv_w  = (const float*)d_in[7];
    const float* fcv_b  = (const float*)d_in[8];
    const float* fco_w  = (const float*)d_in[9];
    const float* fco_b  = (const float*)d_in[10];
    const float* Bmat   = (const float*)d_in[11];
    float* out = (float*)d_out;

    k_part<<<512, 256>>>(x);
    k_stats_weff<<<257, 512>>>(fck_w, wk, fcv_w, wv);
    k_qkv<<<dim3(256+64, BATCH), 128>>>(x, fcq_w, fcq_b, fck_b, fcv_b);
    k_attn<<<dim3(HW/64, BATCH*HEADS), 128>>>(Bmat);
    k_out<<<dim3(HW/16, BATCH), 256>>>(x, fco_w, fco_b, out);
}

// round 14
// speedup vs baseline: 1.2942x; 1.0940x over previous
#include <cuda_runtime.h>
#include <cuda_bf16.h>
#include <math.h>
#include <stdint.h>

// ---------------- problem constants (fixed shapes) ----------------
#define BATCH 8
#define C     64
#define HH    64
#define WW    64
#define HW    4096          // 64*64
#define HEADS 4
#define DK    32
#define HD    128           // HEADS*DK
#define KHW   1024          // 32*32 (stride-2 output)
#define THETA 0.5f
#define EPS_LN 1e-5f
#define NTOT  (BATCH*C*HW)  // 2097152
#define QK_SCALE 0.17677669529663687f  // 1/sqrt(32)

typedef unsigned long long ull;

// packed fp32x2 helpers
__device__ __forceinline__ void fma2(ull& d, ull a, ull b, ull c) {
    asm("fma.rn.f32x2 %0, %1, %2, %3;" : "=l"(d) : "l"(a), "l"(b), "l"(c));
}
__device__ __forceinline__ ull pack2(float lo, float hi) {
    ull r; asm("mov.b64 %0, {%1, %2};" : "=l"(r) : "f"(lo), "f"(hi)); return r;
}
__device__ __forceinline__ void unpack2(float& lo, float& hi, ull v) {
    asm("mov.b64 {%0, %1}, %2;" : "=f"(lo), "=f"(hi) : "l"(v));
}
__device__ __forceinline__ uint32_t bf16x2_of(float a, float b) {
    uint32_t r;
    asm("cvt.rn.satfinite.bf16x2.f32 %0, %1, %2;" : "=r"(r) : "f"(b), "f"(a));
    return r;   // lo=a, hi=b
}

// warp mma: D(16x8,f32) += A(16x16,bf16,row) * B(16x8,bf16,col)
__device__ __forceinline__ void mma_bf16(float* d, const uint32_t* a,
                                         uint32_t b0, uint32_t b1) {
    asm volatile("mma.sync.aligned.m16n8k16.row.col.f32.bf16.bf16.f32 "
        "{%0,%1,%2,%3}, {%4,%5,%6,%7}, {%8,%9}, {%0,%1,%2,%3};"
        : "+f"(d[0]), "+f"(d[1]), "+f"(d[2]), "+f"(d[3])
        : "r"(a[0]), "r"(a[1]), "r"(a[2]), "r"(a[3]), "r"(b0), "r"(b1));
}

// ldmatrix x4 (LDSM)
__device__ __forceinline__ void ldsm_x4(uint32_t& r0, uint32_t& r1,
                                        uint32_t& r2, uint32_t& r3, uint32_t addr) {
    asm volatile("ldmatrix.sync.aligned.m8n8.x4.shared.b16 {%0,%1,%2,%3}, [%4];"
        : "=r"(r0), "=r"(r1), "=r"(r2), "=r"(r3) : "r"(addr));
}
// ldmatrix x4 transposed
__device__ __forceinline__ void ldsm_x4_t(uint32_t& r0, uint32_t& r1,
                                          uint32_t& r2, uint32_t& r3, uint32_t addr) {
    asm volatile("ldmatrix.sync.aligned.m8n8.x4.trans.shared.b16 {%0,%1,%2,%3}, [%4];"
        : "=r"(r0), "=r"(r1), "=r"(r2), "=r"(r3) : "r"(addr));
}

// ---------------- device scratch (static, allowed) ----------------
__device__ float  g_part_s[512];
__device__ float  g_part_s2[512];
__device__ float  g_stats[2];
__device__ __nv_bfloat16 g_weffh[512*256];          // [idx][feat]; feat: K 0..127, V 128..255
__device__ __nv_bfloat16 g_qh[BATCH*HEADS*HW*DK];   // pre-scaled Q, bf16, [bh][q][d]
__device__ __nv_bfloat16 g_kh[BATCH*HEADS*KHW*DK];  // K bf16 [bh][key][d]
__device__ __nv_bfloat16 g_v [BATCH*HEADS*KHW*DK];  // V bf16 [bh][key][d]
__device__ float  g_ctx[BATCH*HW*HD];

// ---------------- launch 0: per-block partial sums (deterministic) ----------------
__global__ void k_part(const float* __restrict__ x)
{
    float s = 0.f, s2 = 0.f;
    int base = blockIdx.x * (NTOT/512);
    for (int i = threadIdx.x; i < NTOT/512; i += 256) {
        float v = x[base + i];
        s  += v;
        s2  = fmaf(v, v, s2);
    }
    #pragma unroll
    for (int off = 16; off; off >>= 1) {
        s  += __shfl_down_sync(0xffffffffu, s,  off);
        s2 += __shfl_down_sync(0xffffffffu, s2, off);
    }
    __shared__ float sh[2][8];
    int lane = threadIdx.x & 31, w = threadIdx.x >> 5;
    if (lane == 0) { sh[0][w] = s; sh[1][w] = s2; }
    __syncthreads();
    if (threadIdx.x == 0) {
        float ts = 0.f, ts2 = 0.f;
        for (int i = 0; i < 8; i++) { ts += sh[0][i]; ts2 += sh[1][i]; }
        g_part_s[blockIdx.x]  = ts;
        g_part_s2[blockIdx.x] = ts2;
    }
}

// ---------------- launch 1: stats finalize (block 0) + weff fold (blocks 1..256) ----------------
// weff: Weff[(ci*8+t)][f] = sum_co fc_w[f][co] * w8[co][ci*8+t], written bf16 [idx][feat]
__global__ void k_stats_weff(const float* __restrict__ fck_w, const float* __restrict__ wk,
                             const float* __restrict__ fcv_w, const float* __restrict__ wv)
{
    if (blockIdx.x == 0) {
        __shared__ double sh[512], sh2[512];
        int t = threadIdx.x;
        sh[t]  = (double)g_part_s[t];
        sh2[t] = (double)g_part_s2[t];
        __syncthreads();
        for (int o = 256; o; o >>= 1) {
            if (t < o) { sh[t] += sh[t+o]; sh2[t] += sh2[t+o]; }
            __syncthreads();
        }
        if (t == 0) {
            double n = (double)NTOT;
            double m = sh[0] / n;
            double var = sh2[0] / n - m*m;
            g_stats[0] = (float)m;
            g_stats[1] = (float)rsqrt(var + (double)EPS_LN);
        }
        return;
    }
    int b2 = blockIdx.x - 1;          // 0..255
    int f  = b2 & 127;
    int kv = b2 >> 7;
    const float* fw = kv ? fcv_w : fck_w;
    const float* w8 = kv ? wv    : wk;
    int idx = threadIdx.x;            // 0..511
    float acc = 0.f;
    #pragma unroll 16
    for (int co = 0; co < 64; co++)
        acc = fmaf(__ldg(&fw[f*64+co]), w8[co*512+idx], acc);
    g_weffh[idx*256 + kv*128 + f] = __float2bfloat16(acc);
}

// ---------------- launch 2: Q projection + tensor-core KV projection ----------------
// blockIdx.x < 256: qproj tile (16 positions, scalar f32x2 path)
// blockIdx.x >= 256: KV projection via mma.sync (32 positions)
__global__ void __launch_bounds__(128) k_qkv(const float* __restrict__ x,
                    const float* __restrict__ fcq_w, const float* __restrict__ fcq_b,
                    const float* __restrict__ fck_b, const float* __restrict__ fcv_b)
{
    __shared__ __align__(16) char smraw[41984];
    int b   = blockIdx.y;
    int tid = threadIdx.x;

    if (blockIdx.x < 256) {
        float* xs = (float*)smraw;            // [c][pos], 64*16
        float* ws = (float*)smraw + 1024;     // [c][f] padded 129
        int p0 = blockIdx.x * 16;
        float mean = g_stats[0], rstd = g_stats[1];

        for (int e = tid; e < 8192; e += 128) {
            int f = e >> 6, c = e & 63;
            ws[c*129+f] = fcq_w[e];
        }
        const float* xb = x + (size_t)b*C*HW;
        for (int e = tid; e < 1024; e += 128) {
            int c = e >> 4, pos = e & 15;
            xs[c*16+pos] = (xb[c*HW + p0 + pos] - mean) * rstd;
        }
        __syncthreads();

        int f = tid;
        float bias = fcq_b[f];
        ull acc2[8];
        #pragma unroll
        for (int i = 0; i < 8; i++) acc2[i] = pack2(bias, bias);
        for (int c = 0; c < 64; c++) {
            float w_ = ws[c*129+f];
            ull w2 = pack2(w_, w_);
            const ull* xr = (const ull*)(xs + c*16);
            #pragma unroll
            for (int i = 0; i < 8; i++) fma2(acc2[i], w2, xr[i], acc2[i]);
        }
        int h = f >> 5, d = f & 31;
        __nv_bfloat16* qb = g_qh + ((size_t)(b*HEADS+h)*HW + p0)*DK + d;
        #pragma unroll
        for (int i = 0; i < 8; i++) {
            float a0, a1; unpack2(a0, a1, acc2[i]);
            qb[(size_t)(2*i)*DK]   = __float2bfloat16(a0 * QK_SCALE);
            qb[(size_t)(2*i+1)*DK] = __float2bfloat16(a1 * QK_SCALE);
        }
    } else {
        // ---- KV projection via tensor cores ----
        __nv_bfloat16* gs    = (__nv_bfloat16*)smraw;            // [32][520]
        __nv_bfloat16* wtile = (__nv_bfloat16*)(smraw + 33280);  // [16][264]
        int p0 = (blockIdx.x - 256) * 32;
        const float* xb = x + (size_t)b*C*HW;

        // gather: gs[pos][idx] = neighbor - theta*center (bf16)
        for (int e = tid; e < 16384; e += 128) {
            int idx = e & 511;
            int pos = e >> 9;
            int ci = idx >> 3, t = idx & 7;
            int pg = p0 + pos;
            int i = pg >> 5, j = pg & 31;
            int cy = i*2, cx = j*2;
            int k9 = (t < 4) ? t : t + 1;      // skip 3x3 center
            int ny = cy + (k9/3) - 1;
            int nx = cx + (k9%3) - 1;
            float ctr = xb[ci*HW + cy*WW + cx];
            float nb = 0.f;
            if (ny >= 0 && ny < HH && nx >= 0 && nx < WW)
                nb = xb[ci*HW + ny*WW + nx];
            gs[pos*520 + idx] = __float2bfloat16(nb - THETA*ctr);
        }

        int l  = tid & 31;
        int pw = (tid >> 5) & 1;      // position half (16 rows)
        int kv = tid >> 6;            // 0 -> K feats, 1 -> V feats
        const float* bias = kv ? fcv_b : fck_b;

        // accumulators: 16 ntiles x 4, init with bias
        float acc[16][4];
        int c0f = 2*(l & 3);
        #pragma unroll
        for (int n = 0; n < 16; n++) {
            float b0 = bias[n*8 + c0f];
            float b1 = bias[n*8 + c0f + 1];
            acc[n][0] = b0; acc[n][1] = b1; acc[n][2] = b0; acc[n][3] = b1;
        }

        uint32_t gs_lane = (uint32_t)__cvta_generic_to_shared(gs)
                         + (uint32_t)((pw*16 + (l & 15))*1040 + (l >> 4)*16);
        uint32_t wt_lane = (uint32_t)__cvta_generic_to_shared(wtile)
                         + (uint32_t)((l & 15)*528 + (l >> 4)*16 + kv*256);
        const uint4* wsrc = (const uint4*)g_weffh;   // 512B/row = 32 uint4 per idx row

        for (int kc = 0; kc < 512; kc += 16) {
            __syncthreads();
            // stage weff tile [16 k][256 feat]: 2x(2 uint4) per thread
            #pragma unroll
            for (int i = 0; i < 2; i++) {
                int e = tid + i*128;
                int r = e >> 4, c = e & 15;   // 16 rows x 16 chunk-pairs
                *(uint4*)((char*)wtile + r*528 + c*32)      = wsrc[(size_t)(kc + r)*32 + c*2];
                *(uint4*)((char*)wtile + r*528 + c*32 + 16) = wsrc[(size_t)(kc + r)*32 + c*2 + 1];
            }
            __syncthreads();
            uint32_t a[4];
            ldsm_x4(a[0], a[1], a[2], a[3], gs_lane + kc*2);
            #pragma unroll
            for (int np = 0; np < 8; np++) {
                uint32_t b0, b1, b2, b3;
                ldsm_x4_t(b0, b1, b2, b3, wt_lane + (uint32_t)(np*32));
                mma_bf16(acc[2*np],     a, b0, b1);
                mma_bf16(acc[2*np + 1], a, b2, b3);
            }
        }

        // store: K/V [bh][key][d] bf16
        __nv_bfloat16* outb = kv ? g_v : g_kh;
        int lq = l >> 2;
        #pragma unroll
        for (int n = 0; n < 16; n++) {
            int f = n*8 + c0f;
            int h = f >> 5, d = f & 31;
            size_t base = ((size_t)(b*HEADS + h)*KHW + p0 + pw*16 + lq)*DK + d;
            *(uint32_t*)(outb + base)          = bf16x2_of(acc[n][0], acc[n][1]);
            *(uint32_t*)(outb + base + 8*DK)   = bf16x2_of(acc[n][2], acc[n][3]);
        }
    }
}

// ---------------- launch 3: attention via mma.sync + ldmatrix ----------------
// CTA: 64 q-rows x one (b,h). 4 warps, warp w owns 16 rows. 5 CTAs/SM.
#define KT 64
__global__ void __launch_bounds__(128, 5) k_attn(const float* __restrict__ Bmat)
{
    __shared__ __align__(16) __nv_bfloat16 Ksm[KT][40];     // keys x dims (stride 80B)
    __shared__ __align__(16) __nv_bfloat16 Vsm[KT][40];     // keys x dims (stride 80B)
    int tid = threadIdx.x;
    int w = tid >> 5, l = tid & 31;
    int g = l >> 2, t = l & 3;
    int bh = blockIdx.y, h = bh & 3;
    int q0 = blockIdx.x * 64 + w * 16;

    // Q a-frags (once): [kchunk][4] for this warp's 16 rows
    uint32_t qa[2][4];
    const __nv_bfloat16* Qb = g_qh + ((size_t)bh*HW + q0)*DK;
    #pragma unroll
    for (int kc = 0; kc < 2; kc++) {
        qa[kc][0] = *(const uint32_t*)(Qb + (size_t)g*DK     + kc*16 + 2*t);
        qa[kc][1] = *(const uint32_t*)(Qb + (size_t)(g+8)*DK + kc*16 + 2*t);
        qa[kc][2] = *(const uint32_t*)(Qb + (size_t)g*DK     + kc*16 + 8 + 2*t);
        qa[kc][3] = *(const uint32_t*)(Qb + (size_t)(g+8)*DK + kc*16 + 8 + 2*t);
    }

    float o[4][4];                    // [dim-block][frag]
    float lsum[2];                    // rows g / g+8
    lsum[0] = lsum[1] = 0.f;
    #pragma unroll
    for (int db = 0; db < 4; db++)
        o[db][0] = o[db][1] = o[db][2] = o[db][3] = 0.f;

    // per-lane ldmatrix base addresses
    uint32_t ksm0 = (uint32_t)__cvta_generic_to_shared(&Ksm[0][0]);
    uint32_t vsm0 = (uint32_t)__cvta_generic_to_shared(&Vsm[0][0]);
    uint32_t k_lane = ksm0 + (uint32_t)((l & 7)*80 + (l >> 3)*16);
    uint32_t v_lane = vsm0 + (uint32_t)((l & 15)*80 + (l >> 4)*16);

    const float* Bb = Bmat + (size_t)h*HW*KHW;
    const uint4* kg4 = (const uint4*)(g_kh + (size_t)bh*KHW*DK);   // 4 uint4 per key
    const uint4* vg4 = (const uint4*)(g_v  + (size_t)bh*KHW*DK);   // 4 uint4 per key

    for (int c0 = 0; c0 < KHW; c0 += KT) {
        __syncthreads();
        // K tile: 256 uint4 chunks (64 keys x 64B)
        #pragma unroll
        for (int i = 0; i < 2; i++) {
            int e = tid + i*128;
            int r = e >> 2, c = e & 3;
            *(uint4*)((char*)&Ksm[0][0] + r*80 + c*16) = kg4[(size_t)(c0 + r)*4 + c];
        }
        // V tile: same layout
        #pragma unroll
        for (int i = 0; i < 2; i++) {
            int e = tid + i*128;
            int r = e >> 2, c = e & 3;
            *(uint4*)((char*)&Vsm[0][0] + r*80 + c*16) = vg4[(size_t)(c0 + r)*4 + c];
        }
        __syncthreads();

        #pragma unroll
        for (int half = 0; half < 2; half++) {
            int c32 = half * 32;
            // ---- S = Q K^T over 32 keys (ldmatrix b-frags) ----
            float s[4][4];
            #pragma unroll
            for (int nb = 0; nb < 4; nb++)
                s[nb][0] = s[nb][1] = s[nb][2] = s[nb][3] = 0.f;
            #pragma unroll
            for (int nb = 0; nb < 4; nb++) {
                uint32_t b0, b1, b2, b3;
                ldsm_x4(b0, b1, b2, b3, k_lane + (uint32_t)((c32 + 8*nb)*80));
                mma_bf16(s[nb], qa[0], b0, b1);
                mma_bf16(s[nb], qa[1], b2, b3);
            }
            // ---- epilogue: +bias, exp, l, pack P ----
            uint32_t pa[2][4];
            #pragma unroll
            for (int nb = 0; nb < 4; nb++) {
                int row = q0 + g;
                size_t bidx = (size_t)row*KHW + c0 + c32 + 8*nb + 2*t;
                float2 bv0 = *(const float2*)(Bb + bidx);
                float2 bv1 = *(const float2*)(Bb + bidx + (size_t)8*KHW);
                float p0 = __expf(s[nb][0] + bv0.x);
                float p1 = __expf(s[nb][1] + bv0.y);
                float p2 = __expf(s[nb][2] + bv1.x);
                float p3 = __expf(s[nb][3] + bv1.y);
                lsum[0] += (p0 + p1);
                lsum[1] += (p2 + p3);
                int u = nb >> 1, odd = nb & 1;
                pa[u][2*odd]     = bf16x2_of(p0, p1);
                pa[u][2*odd + 1] = bf16x2_of(p2, p3);
            }
            // ---- O += P V (trans ldmatrix b-frags from [key][dim]) ----
            #pragma unroll
            for (int u = 0; u < 2; u++)
                #pragma unroll
                for (int dp = 0; dp < 2; dp++) {
                    uint32_t b0, b1, b2, b3;
                    ldsm_x4_t(b0, b1, b2, b3,
                              v_lane + (uint32_t)((c32 + 16*u)*80 + dp*32));
                    mma_bf16(o[2*dp],     pa[u], b0, b1);
                    mma_bf16(o[2*dp + 1], pa[u], b2, b3);
                }
        }
    }

    // reduce l over the t-quad, normalize, store ctx
    #pragma unroll
    for (int r = 0; r < 2; r++) {
        float v = lsum[r];
        v += __shfl_xor_sync(0xffffffffu, v, 1);
        v += __shfl_xor_sync(0xffffffffu, v, 2);
        lsum[r] = 1.f / v;
    }
    int b = bh >> 2;
    int row = q0 + g;
    #pragma unroll
    for (int db = 0; db < 4; db++) {
        int dim = h*DK + 8*db + 2*t;
        float2 lo = make_float2(o[db][0]*lsum[0], o[db][1]*lsum[0]);
        float2 hi = make_float2(o[db][2]*lsum[1], o[db][3]*lsum[1]);
        *(float2*)(g_ctx + ((size_t)b*HW + row)*HD + dim)     = lo;
        *(float2*)(g_ctx + ((size_t)b*HW + row + 8)*HD + dim) = hi;
    }
}

// ---------------- launch 4: output projection + residual, f32x2 packed ----------------
__global__ void k_out(const float* __restrict__ x,
                      const float* __restrict__ fco_w,
                      const float* __restrict__ fco_b,
                      float* __restrict__ out)
{
    __shared__ float cs[16*128];
    __shared__ float ws2[64*130];
    int b   = blockIdx.y;
    int p0  = blockIdx.x * 16;
    int tid = threadIdx.x;

    for (int e = tid; e < 8192; e += 256) {
        int ch = e >> 7, k = e & 127;
        ws2[ch*130+k] = fco_w[e];
    }
    const float* ctx = g_ctx + ((size_t)b*HW + p0)*HD;
    for (int e = tid; e < 2048; e += 256) cs[e] = ctx[e];
    __syncthreads();

    int ch = tid & 63;
    int pg = tid >> 6;
    ull acc2[4];
    #pragma unroll
    for (int pi = 0; pi < 4; pi++) acc2[pi] = 0ull;
    const ull* wr = (const ull*)(ws2 + ch*130);
    #pragma unroll 4
    for (int kp = 0; kp < 64; kp++) {
        ull w2 = wr[kp];
        #pragma unroll
        for (int pi = 0; pi < 4; pi++) {
            ull c2 = *(const ull*)(cs + (pg*4+pi)*128 + 2*kp);
            fma2(acc2[pi], w2, c2, acc2[pi]);
        }
    }
    float bias = fco_b[ch];
    #pragma unroll
    for (int pi = 0; pi < 4; pi++) {
        float a0, a1; unpack2(a0, a1, acc2[pi]);
        int pos = pg*4 + pi;
        size_t oi = (size_t)b*(C*HW) + (size_t)(p0+pos)*64 + ch;
        out[oi] = (a0 + a1) + bias + x[oi];
    }
}

// ---------------- launcher (5 launches; k_attn is launch idx 3) ----------------
extern "C" void kernel_launch(void* const* d_in, const int* in_sizes, int n_in,
                              void* d_out, int out_size)
{
    (void)n_in; (void)out_size; (void)in_sizes;
    const float* x      = (const float*)d_in[0];
    const float* wk     = (const float*)d_in[1];
    const float* wv     = (const float*)d_in[2];
    const float* fcq_w  = (const float*)d_in[3];
    const float* fcq_b  = (const float*)d_in[4];
    const float* fck_w  = (const float*)d_in[5];
    const float* fck_b  = (const float*)d_in[6];
    const float* fcv_w  = (const float*)d_in[7];
    const float* fcv_b  = (const float*)d_in[8];
    const float* fco_w  = (const float*)d_in[9];
    const float* fco_b  = (const float*)d_in[10];
    const float* Bmat   = (const float*)d_in[11];
    float* out = (float*)d_out;

    k_part<<<512, 256>>>(x);
    k_stats_weff<<<257, 512>>>(fck_w, wk, fcv_w, wv);
    k_qkv<<<dim3(256+32, BATCH), 128>>>(x, fcq_w, fcq_b, fck_b, fcv_b);
    k_attn<<<dim3(HW/64, BATCH*HEADS), 128>>>(Bmat);
    k_out<<<dim3(HW/16, BATCH), 256>>>(x, fco_w, fco_b, out);
}

// round 15
// speedup vs baseline: 1.4405x; 1.1130x over previous
#include <cuda_runtime.h>
#include <cuda_bf16.h>
#include <math.h>
#include <stdint.h>

// ---------------- problem constants (fixed shapes) ----------------
#define BATCH 8
#define C     64
#define HH    64
#define WW    64
#define HW    4096          // 64*64
#define HEADS 4
#define DK    32
#define HD    128           // HEADS*DK
#define KHW   1024          // 32*32 (stride-2 output)
#define THETA 0.5f
#define EPS_LN 1e-5f
#define NTOT  (BATCH*C*HW)  // 2097152
#define QK_SCALE 0.17677669529663687f  // 1/sqrt(32)

typedef unsigned long long ull;

// packed fp32x2 helpers
__device__ __forceinline__ void fma2(ull& d, ull a, ull b, ull c) {
    asm("fma.rn.f32x2 %0, %1, %2, %3;" : "=l"(d) : "l"(a), "l"(b), "l"(c));
}
__device__ __forceinline__ void unpack2(float& lo, float& hi, ull v) {
    asm("mov.b64 {%0, %1}, %2;" : "=f"(lo), "=f"(hi) : "l"(v));
}
__device__ __forceinline__ uint32_t bf16x2_of(float a, float b) {
    uint32_t r;
    asm("cvt.rn.satfinite.bf16x2.f32 %0, %1, %2;" : "=r"(r) : "f"(b), "f"(a));
    return r;   // lo=a, hi=b
}

// warp mma: D(16x8,f32) += A(16x16,bf16,row) * B(16x8,bf16,col)
__device__ __forceinline__ void mma_bf16(float* d, const uint32_t* a,
                                         uint32_t b0, uint32_t b1) {
    asm volatile("mma.sync.aligned.m16n8k16.row.col.f32.bf16.bf16.f32 "
        "{%0,%1,%2,%3}, {%4,%5,%6,%7}, {%8,%9}, {%0,%1,%2,%3};"
        : "+f"(d[0]), "+f"(d[1]), "+f"(d[2]), "+f"(d[3])
        : "r"(a[0]), "r"(a[1]), "r"(a[2]), "r"(a[3]), "r"(b0), "r"(b1));
}

// ldmatrix x4 (LDSM)
__device__ __forceinline__ void ldsm_x4(uint32_t& r0, uint32_t& r1,
                                        uint32_t& r2, uint32_t& r3, uint32_t addr) {
    asm volatile("ldmatrix.sync.aligned.m8n8.x4.shared.b16 {%0,%1,%2,%3}, [%4];"
        : "=r"(r0), "=r"(r1), "=r"(r2), "=r"(r3) : "r"(addr));
}
// ldmatrix x4 transposed
__device__ __forceinline__ void ldsm_x4_t(uint32_t& r0, uint32_t& r1,
                                          uint32_t& r2, uint32_t& r3, uint32_t addr) {
    asm volatile("ldmatrix.sync.aligned.m8n8.x4.trans.shared.b16 {%0,%1,%2,%3}, [%4];"
        : "=r"(r0), "=r"(r1), "=r"(r2), "=r"(r3) : "r"(addr));
}

// ---------------- device scratch (static, allowed) ----------------
__device__ float  g_part_s[512];
__device__ float  g_part_s2[512];
__device__ float  g_stats[2];
__device__ __nv_bfloat16 g_weffh[512*256];          // [idx][feat]; feat: K 0..127, V 128..255
__device__ __nv_bfloat16 g_wqh[64*128];             // fcq_w bf16, [c][f]
__device__ __nv_bfloat16 g_qh[BATCH*HEADS*HW*DK];   // pre-scaled Q, bf16, [bh][q][d]
__device__ __nv_bfloat16 g_kh[BATCH*HEADS*KHW*DK];  // K bf16 [bh][key][d]
__device__ __nv_bfloat16 g_v [BATCH*HEADS*KHW*DK];  // V bf16 [bh][key][d]
__device__ float  g_ctx[BATCH*HW*HD];

// ---------------- launch 0: per-block partial sums (deterministic) ----------------
__global__ void k_part(const float* __restrict__ x)
{
    float s = 0.f, s2 = 0.f;
    int base = blockIdx.x * (NTOT/512);
    for (int i = threadIdx.x; i < NTOT/512; i += 256) {
        float v = x[base + i];
        s  += v;
        s2  = fmaf(v, v, s2);
    }
    #pragma unroll
    for (int off = 16; off; off >>= 1) {
        s  += __shfl_down_sync(0xffffffffu, s,  off);
        s2 += __shfl_down_sync(0xffffffffu, s2, off);
    }
    __shared__ float sh[2][8];
    int lane = threadIdx.x & 31, w = threadIdx.x >> 5;
    if (lane == 0) { sh[0][w] = s; sh[1][w] = s2; }
    __syncthreads();
    if (threadIdx.x == 0) {
        float ts = 0.f, ts2 = 0.f;
        for (int i = 0; i < 8; i++) { ts += sh[0][i]; ts2 += sh[1][i]; }
        g_part_s[blockIdx.x]  = ts;
        g_part_s2[blockIdx.x] = ts2;
    }
}

// ---------------- launch 1: stats (blk 0) + weff fold (blks 1..256) + fcq cvt (blk 257) ----------------
__global__ void k_stats_weff(const float* __restrict__ fck_w, const float* __restrict__ wk,
                             const float* __restrict__ fcv_w, const float* __restrict__ wv,
                             const float* __restrict__ fcq_w)
{
    if (blockIdx.x == 0) {
        __shared__ double sh[512], sh2[512];
        int t = threadIdx.x;
        sh[t]  = (double)g_part_s[t];
        sh2[t] = (double)g_part_s2[t];
        __syncthreads();
        for (int o = 256; o; o >>= 1) {
            if (t < o) { sh[t] += sh[t+o]; sh2[t] += sh2[t+o]; }
            __syncthreads();
        }
        if (t == 0) {
            double n = (double)NTOT;
            double m = sh[0] / n;
            double var = sh2[0] / n - m*m;
            g_stats[0] = (float)m;
            g_stats[1] = (float)rsqrt(var + (double)EPS_LN);
        }
        return;
    }
    if (blockIdx.x == 257) {
        // fcq_w [f][c] f32 -> g_wqh [c][f] bf16
        for (int e = threadIdx.x; e < 8192; e += 512) {
            int c = e >> 7, f = e & 127;
            g_wqh[c*128 + f] = __float2bfloat16(fcq_w[f*64 + c]);
        }
        return;
    }
    int b2 = blockIdx.x - 1;          // 0..255
    int f  = b2 & 127;
    int kv = b2 >> 7;
    const float* fw = kv ? fcv_w : fck_w;
    const float* w8 = kv ? wv    : wk;
    int idx = threadIdx.x;            // 0..511
    float acc = 0.f;
    #pragma unroll 16
    for (int co = 0; co < 64; co++)
        acc = fmaf(__ldg(&fw[f*64+co]), w8[co*512+idx], acc);
    g_weffh[idx*256 + kv*128 + f] = __float2bfloat16(acc);
}

// ---------------- launch 2: tensor-core Q projection + tensor-core KV projection ----------------
// blockIdx.x < 128:  Q-proj GEMM (32 positions)
// blockIdx.x >= 128: KV-proj GEMM (32 positions)
__global__ void __launch_bounds__(128) k_qkv(const float* __restrict__ x,
                    const float* __restrict__ fcq_b,
                    const float* __restrict__ fck_b, const float* __restrict__ fcv_b)
{
    __shared__ __align__(16) char smraw[41984];
    int b   = blockIdx.y;
    int tid = threadIdx.x;
    int l   = tid & 31;
    int pw  = (tid >> 5) & 1;     // position half (16 rows)
    int c0f = 2*(l & 3);
    int lq  = l >> 2;
    const float* xb = x + (size_t)b*C*HW;

    if (blockIdx.x < 128) {
        // ---- Q projection via tensor cores: [32 pos][64 c] x [64 c][128 f] ----
        __nv_bfloat16* xn = (__nv_bfloat16*)smraw;            // [32][72] stride 144B
        __nv_bfloat16* wq = (__nv_bfloat16*)(smraw + 4608);   // [64][136] stride 272B
        int p0 = blockIdx.x * 32;
        float mean = g_stats[0], rstd = g_stats[1];

        for (int e = tid; e < 2048; e += 128) {
            int c = e >> 5, pos = e & 31;
            xn[pos*72 + c] = __float2bfloat16((xb[c*HW + p0 + pos] - mean) * rstd);
        }
        const uint4* wqsrc = (const uint4*)g_wqh;   // 16 uint4 per c-row
        #pragma unroll
        for (int i = 0; i < 8; i++) {
            int e = tid + i*128;
            int r = e >> 4, ch = e & 15;
            *(uint4*)((char*)wq + r*272 + ch*16) = wqsrc[r*16 + ch];
        }
        __syncthreads();

        int fh = tid >> 6;            // feature half: 64 feats each
        const float* bias = fcq_b + fh*64;
        float acc[8][4];
        #pragma unroll
        for (int n = 0; n < 8; n++) {
            float b0 = bias[n*8 + c0f];
            float b1 = bias[n*8 + c0f + 1];
            acc[n][0] = b0; acc[n][1] = b1; acc[n][2] = b0; acc[n][3] = b1;
        }
        uint32_t xq_lane = (uint32_t)__cvta_generic_to_shared(xn)
                         + (uint32_t)((pw*16 + (l & 15))*144 + (l >> 4)*16);
        uint32_t wq_lane = (uint32_t)__cvta_generic_to_shared(wq)
                         + (uint32_t)((l & 15)*272 + (l >> 4)*16 + fh*128);
        #pragma unroll
        for (int kcI = 0; kcI < 4; kcI++) {
            uint32_t a[4];
            ldsm_x4(a[0], a[1], a[2], a[3], xq_lane + kcI*32);
            #pragma unroll
            for (int np = 0; np < 4; np++) {
                uint32_t b0, b1, b2, b3;
                ldsm_x4_t(b0, b1, b2, b3, wq_lane + (uint32_t)(kcI*4352 + np*32));
                mma_bf16(acc[2*np],     a, b0, b1);
                mma_bf16(acc[2*np + 1], a, b2, b3);
            }
        }
        #pragma unroll
        for (int n = 0; n < 8; n++) {
            int f = fh*64 + n*8 + c0f;
            int h = f >> 5, d = f & 31;
            size_t base = ((size_t)(b*HEADS + h)*HW + p0 + pw*16 + lq)*DK + d;
            *(uint32_t*)(g_qh + base)        = bf16x2_of(acc[n][0]*QK_SCALE, acc[n][1]*QK_SCALE);
            *(uint32_t*)(g_qh + base + 8*DK) = bf16x2_of(acc[n][2]*QK_SCALE, acc[n][3]*QK_SCALE);
        }
    } else {
        // ---- KV projection via tensor cores ----
        __nv_bfloat16* gs    = (__nv_bfloat16*)smraw;            // [32][520]
        __nv_bfloat16* wtile = (__nv_bfloat16*)(smraw + 33280);  // [16][264]
        int p0 = (blockIdx.x - 128) * 32;

        // gather: per (pos, ci) compute all 8 taps, one uint4 store
        for (int e = tid; e < 2048; e += 128) {
            int pos = e & 31;
            int ci  = e >> 5;
            int pg = p0 + pos;
            int i = pg >> 5, j = pg & 31;
            int cy = i*2, cx = j*2;
            const float* xc = xb + ci*HW;
            float ctr = xc[cy*WW + cx] * THETA;
            bool top = (i > 0);
            bool lft = (j > 0);
            int up = (cy-1)*WW, md = cy*WW, dn = (cy+1)*WW;
            float t0 = (top && lft) ? xc[up+cx-1] : 0.f;
            float t1 = top ? xc[up+cx]   : 0.f;
            float t2 = top ? xc[up+cx+1] : 0.f;
            float t3 = lft ? xc[md+cx-1] : 0.f;
            float t4 = xc[md+cx+1];
            float t5 = lft ? xc[dn+cx-1] : 0.f;
            float t6 = xc[dn+cx];
            float t7 = xc[dn+cx+1];
            uint4 v;
            v.x = bf16x2_of(t0 - ctr, t1 - ctr);
            v.y = bf16x2_of(t2 - ctr, t3 - ctr);
            v.z = bf16x2_of(t4 - ctr, t5 - ctr);
            v.w = bf16x2_of(t6 - ctr, t7 - ctr);
            *(uint4*)((char*)gs + pos*1040 + ci*16) = v;
        }

        int kv = tid >> 6;            // 0 -> K feats, 1 -> V feats
        const float* bias = kv ? fcv_b : fck_b;

        float acc[16][4];
        #pragma unroll
        for (int n = 0; n < 16; n++) {
            float b0 = bias[n*8 + c0f];
            float b1 = bias[n*8 + c0f + 1];
            acc[n][0] = b0; acc[n][1] = b1; acc[n][2] = b0; acc[n][3] = b1;
        }

        uint32_t gs_lane = (uint32_t)__cvta_generic_to_shared(gs)
                         + (uint32_t)((pw*16 + (l & 15))*1040 + (l >> 4)*16);
        uint32_t wt_lane = (uint32_t)__cvta_generic_to_shared(wtile)
                         + (uint32_t)((l & 15)*528 + (l >> 4)*16 + kv*256);
        const uint4* wsrc = (const uint4*)g_weffh;   // 512B/row = 32 uint4 per idx row

        for (int kc = 0; kc < 512; kc += 16) {
            __syncthreads();
            #pragma unroll
            for (int i = 0; i < 2; i++) {
                int e = tid + i*128;
                int r = e >> 4, c = e & 15;
                *(uint4*)((char*)wtile + r*528 + c*32)      = wsrc[(size_t)(kc + r)*32 + c*2];
                *(uint4*)((char*)wtile + r*528 + c*32 + 16) = wsrc[(size_t)(kc + r)*32 + c*2 + 1];
            }
            __syncthreads();
            uint32_t a[4];
            ldsm_x4(a[0], a[1], a[2], a[3], gs_lane + kc*2);
            #pragma unroll
            for (int np = 0; np < 8; np++) {
                uint32_t b0, b1, b2, b3;
                ldsm_x4_t(b0, b1, b2, b3, wt_lane + (uint32_t)(np*32));
                mma_bf16(acc[2*np],     a, b0, b1);
                mma_bf16(acc[2*np + 1], a, b2, b3);
            }
        }

        __nv_bfloat16* outb = kv ? g_v : g_kh;
        #pragma unroll
        for (int n = 0; n < 16; n++) {
            int f = n*8 + c0f;
            int h = f >> 5, d = f & 31;
            size_t base = ((size_t)(b*HEADS + h)*KHW + p0 + pw*16 + lq)*DK + d;
            *(uint32_t*)(outb + base)        = bf16x2_of(acc[n][0], acc[n][1]);
            *(uint32_t*)(outb + base + 8*DK) = bf16x2_of(acc[n][2], acc[n][3]);
        }
    }
}

// ---------------- launch 3: attention via mma.sync + ldmatrix ----------------
// CTA: 64 q-rows x one (b,h). 4 warps, warp w owns 16 rows. 5 CTAs/SM.
#define KT 64
__global__ void __launch_bounds__(128, 5) k_attn(const float* __restrict__ Bmat)
{
    __shared__ __align__(16) __nv_bfloat16 Ksm[KT][40];     // keys x dims (stride 80B)
    __shared__ __align__(16) __nv_bfloat16 Vsm[KT][40];     // keys x dims (stride 80B)
    int tid = threadIdx.x;
    int w = tid >> 5, l = tid & 31;
    int g = l >> 2, t = l & 3;
    int bh = blockIdx.y, h = bh & 3;
    int q0 = blockIdx.x * 64 + w * 16;

    // Q a-frags (once): [kchunk][4] for this warp's 16 rows
    uint32_t qa[2][4];
    const __nv_bfloat16* Qb = g_qh + ((size_t)bh*HW + q0)*DK;
    #pragma unroll
    for (int kc = 0; kc < 2; kc++) {
        qa[kc][0] = *(const uint32_t*)(Qb + (size_t)g*DK     + kc*16 + 2*t);
        qa[kc][1] = *(const uint32_t*)(Qb + (size_t)(g+8)*DK + kc*16 + 2*t);
        qa[kc][2] = *(const uint32_t*)(Qb + (size_t)g*DK     + kc*16 + 8 + 2*t);
        qa[kc][3] = *(const uint32_t*)(Qb + (size_t)(g+8)*DK + kc*16 + 8 + 2*t);
    }

    float o[4][4];                    // [dim-block][frag]
    float lsum[2];                    // rows g / g+8
    lsum[0] = lsum[1] = 0.f;
    #pragma unroll
    for (int db = 0; db < 4; db++)
        o[db][0] = o[db][1] = o[db][2] = o[db][3] = 0.f;

    // per-lane ldmatrix base addresses
    uint32_t ksm0 = (uint32_t)__cvta_generic_to_shared(&Ksm[0][0]);
    uint32_t vsm0 = (uint32_t)__cvta_generic_to_shared(&Vsm[0][0]);
    uint32_t k_lane = ksm0 + (uint32_t)((l & 7)*80 + (l >> 3)*16);
    uint32_t v_lane = vsm0 + (uint32_t)((l & 15)*80 + (l >> 4)*16);

    const float* Bb = Bmat + (size_t)h*HW*KHW;
    const uint4* kg4 = (const uint4*)(g_kh + (size_t)bh*KHW*DK);   // 4 uint4 per key
    const uint4* vg4 = (const uint4*)(g_v  + (size_t)bh*KHW*DK);   // 4 uint4 per key

    for (int c0 = 0; c0 < KHW; c0 += KT) {
        __syncthreads();
        // K tile: 256 uint4 chunks (64 keys x 64B)
        #pragma unroll
        for (int i = 0; i < 2; i++) {
            int e = tid + i*128;
            int r = e >> 2, c = e & 3;
            *(uint4*)((char*)&Ksm[0][0] + r*80 + c*16) = kg4[(size_t)(c0 + r)*4 + c];
        }
        // V tile: same layout
        #pragma unroll
        for (int i = 0; i < 2; i++) {
            int e = tid + i*128;
            int r = e >> 2, c = e & 3;
            *(uint4*)((char*)&Vsm[0][0] + r*80 + c*16) = vg4[(size_t)(c0 + r)*4 + c];
        }
        __syncthreads();

        #pragma unroll
        for (int half = 0; half < 2; half++) {
            int c32 = half * 32;
            // ---- S = Q K^T over 32 keys (ldmatrix b-frags) ----
            float s[4][4];
            #pragma unroll
            for (int nb = 0; nb < 4; nb++)
                s[nb][0] = s[nb][1] = s[nb][2] = s[nb][3] = 0.f;
            #pragma unroll
            for (int nb = 0; nb < 4; nb++) {
                uint32_t b0, b1, b2, b3;
                ldsm_x4(b0, b1, b2, b3, k_lane + (uint32_t)((c32 + 8*nb)*80));
                mma_bf16(s[nb], qa[0], b0, b1);
                mma_bf16(s[nb], qa[1], b2, b3);
            }
            // ---- epilogue: +bias, exp, l, pack P ----
            uint32_t pa[2][4];
            #pragma unroll
            for (int nb = 0; nb < 4; nb++) {
                int row = q0 + g;
                size_t bidx = (size_t)row*KHW + c0 + c32 + 8*nb + 2*t;
                float2 bv0 = *(const float2*)(Bb + bidx);
                float2 bv1 = *(const float2*)(Bb + bidx + (size_t)8*KHW);
                float p0 = __expf(s[nb][0] + bv0.x);
                float p1 = __expf(s[nb][1] + bv0.y);
                float p2 = __expf(s[nb][2] + bv1.x);
                float p3 = __expf(s[nb][3] + bv1.y);
                lsum[0] += (p0 + p1);
                lsum[1] += (p2 + p3);
                int u = nb >> 1, odd = nb & 1;
                pa[u][2*odd]     = bf16x2_of(p0, p1);
                pa[u][2*odd + 1] = bf16x2_of(p2, p3);
            }
            // ---- O += P V (trans ldmatrix b-frags from [key][dim]) ----
            #pragma unroll
            for (int u = 0; u < 2; u++)
                #pragma unroll
                for (int dp = 0; dp < 2; dp++) {
                    uint32_t b0, b1, b2, b3;
                    ldsm_x4_t(b0, b1, b2, b3,
                              v_lane + (uint32_t)((c32 + 16*u)*80 + dp*32));
                    mma_bf16(o[2*dp],     pa[u], b0, b1);
                    mma_bf16(o[2*dp + 1], pa[u], b2, b3);
                }
        }
    }

    // reduce l over the t-quad, normalize, store ctx
    #pragma unroll
    for (int r = 0; r < 2; r++) {
        float v = lsum[r];
        v += __shfl_xor_sync(0xffffffffu, v, 1);
        v += __shfl_xor_sync(0xffffffffu, v, 2);
        lsum[r] = 1.f / v;
    }
    int b = bh >> 2;
    int row = q0 + g;
    #pragma unroll
    for (int db = 0; db < 4; db++) {
        int dim = h*DK + 8*db + 2*t;
        float2 lo = make_float2(o[db][0]*lsum[0], o[db][1]*lsum[0]);
        float2 hi = make_float2(o[db][2]*lsum[1], o[db][3]*lsum[1]);
        *(float2*)(g_ctx + ((size_t)b*HW + row)*HD + dim)     = lo;
        *(float2*)(g_ctx + ((size_t)b*HW + row + 8)*HD + dim) = hi;
    }
}

// ---------------- launch 4: output projection + residual, f32x2 packed ----------------
__global__ void k_out(const float* __restrict__ x,
                      const float* __restrict__ fco_w,
                      const float* __restrict__ fco_b,
                      float* __restrict__ out)
{
    __shared__ float cs[16*128];
    __shared__ float ws2[64*130];
    int b   = blockIdx.y;
    int p0  = blockIdx.x * 16;
    int tid = threadIdx.x;

    for (int e = tid; e < 8192; e += 256) {
        int ch = e >> 7, k = e & 127;
        ws2[ch*130+k] = fco_w[e];
    }
    const float* ctx = g_ctx + ((size_t)b*HW + p0)*HD;
    for (int e = tid; e < 2048; e += 256) cs[e] = ctx[e];
    __syncthreads();

    int ch = tid & 63;
    int pg = tid >> 6;
    ull acc2[4];
    #pragma unroll
    for (int pi = 0; pi < 4; pi++) acc2[pi] = 0ull;
    const ull* wr = (const ull*)(ws2 + ch*130);
    #pragma unroll 4
    for (int kp = 0; kp < 64; kp++) {
        ull w2 = wr[kp];
        #pragma unroll
        for (int pi = 0; pi < 4; pi++) {
            ull c2 = *(const ull*)(cs + (pg*4+pi)*128 + 2*kp);
            fma2(acc2[pi], w2, c2, acc2[pi]);
        }
    }
    float bias = fco_b[ch];
    #pragma unroll
    for (int pi = 0; pi < 4; pi++) {
        float a0, a1; unpack2(a0, a1, acc2[pi]);
        int pos = pg*4 + pi;
        size_t oi = (size_t)b*(C*HW) + (size_t)(p0+pos)*64 + ch;
        out[oi] = (a0 + a1) + bias + x[oi];
    }
}

// ---------------- launcher (5 launches; k_attn is launch idx 3) ----------------
extern "C" void kernel_launch(void* const* d_in, const int* in_sizes, int n_in,
                              void* d_out, int out_size)
{
    (void)n_in; (void)out_size; (void)in_sizes;
    const float* x      = (const float*)d_in[0];
    const float* wk     = (const float*)d_in[1];
    const float* wv     = (const float*)d_in[2];
    const float* fcq_w  = (const float*)d_in[3];
    const float* fcq_b  = (const float*)d_in[4];
    const float* fck_w  = (const float*)d_in[5];
    const float* fck_b  = (const float*)d_in[6];
    const float* fcv_w  = (const float*)d_in[7];
    const float* fcv_b  = (const float*)d_in[8];
    const float* fco_w  = (const float*)d_in[9];
    const float* fco_b  = (const float*)d_in[10];
    const float* Bmat   = (const float*)d_in[11];
    float* out = (float*)d_out;

    k_part<<<512, 256>>>(x);
    k_stats_weff<<<258, 512>>>(fck_w, wk, fcv_w, wv, fcq_w);
    k_qkv<<<dim3(128+32, BATCH), 128>>>(x, fcq_b, fck_b, fcv_b);
    k_attn<<<dim3(HW/64, BATCH*HEADS), 128>>>(Bmat);
    k_out<<<dim3(HW/16, BATCH), 256>>>(x, fco_w, fco_b, out);
}

// round 16
// speedup vs baseline: 1.5290x; 1.0615x over previous
#include <cuda_runtime.h>
#include <cuda_bf16.h>
#include <math.h>
#include <stdint.h>

// ---------------- problem constants (fixed shapes) ----------------
#define BATCH 8
#define C     64
#define HH    64
#define WW    64
#define HW    4096          // 64*64
#define HEADS 4
#define DK    32
#define HD    128           // HEADS*DK
#define KHW   1024          // 32*32 (stride-2 output)
#define THETA 0.5f
#define EPS_LN 1e-5f
#define NTOT  (BATCH*C*HW)  // 2097152
#define QK_SCALE 0.17677669529663687f  // 1/sqrt(32)

typedef unsigned long long ull;

// packed fp32x2 helpers
__device__ __forceinline__ void fma2(ull& d, ull a, ull b, ull c) {
    asm("fma.rn.f32x2 %0, %1, %2, %3;" : "=l"(d) : "l"(a), "l"(b), "l"(c));
}
__device__ __forceinline__ void unpack2(float& lo, float& hi, ull v) {
    asm("mov.b64 {%0, %1}, %2;" : "=f"(lo), "=f"(hi) : "l"(v));
}
__device__ __forceinline__ uint32_t bf16x2_of(float a, float b) {
    uint32_t r;
    asm("cvt.rn.satfinite.bf16x2.f32 %0, %1, %2;" : "=r"(r) : "f"(b), "f"(a));
    return r;   // lo=a, hi=b
}

// warp mma: D(16x8,f32) += A(16x16,bf16,row) * B(16x8,bf16,col)
__device__ __forceinline__ void mma_bf16(float* d, const uint32_t* a,
                                         uint32_t b0, uint32_t b1) {
    asm volatile("mma.sync.aligned.m16n8k16.row.col.f32.bf16.bf16.f32 "
        "{%0,%1,%2,%3}, {%4,%5,%6,%7}, {%8,%9}, {%0,%1,%2,%3};"
        : "+f"(d[0]), "+f"(d[1]), "+f"(d[2]), "+f"(d[3])
        : "r"(a[0]), "r"(a[1]), "r"(a[2]), "r"(a[3]), "r"(b0), "r"(b1));
}

// ldmatrix x4 (LDSM)
__device__ __forceinline__ void ldsm_x4(uint32_t& r0, uint32_t& r1,
                                        uint32_t& r2, uint32_t& r3, uint32_t addr) {
    asm volatile("ldmatrix.sync.aligned.m8n8.x4.shared.b16 {%0,%1,%2,%3}, [%4];"
        : "=r"(r0), "=r"(r1), "=r"(r2), "=r"(r3) : "r"(addr));
}
// ldmatrix x4 transposed
__device__ __forceinline__ void ldsm_x4_t(uint32_t& r0, uint32_t& r1,
                                          uint32_t& r2, uint32_t& r3, uint32_t addr) {
    asm volatile("ldmatrix.sync.aligned.m8n8.x4.trans.shared.b16 {%0,%1,%2,%3}, [%4];"
        : "=r"(r0), "=r"(r1), "=r"(r2), "=r"(r3) : "r"(addr));
}

// cp.async 16B
__device__ __forceinline__ void cp16(uint32_t smem_dst, const void* gsrc) {
    asm volatile("cp.async.cg.shared.global [%0], [%1], 16;"
                 :: "r"(smem_dst), "l"(gsrc) : "memory");
}
__device__ __forceinline__ void cp_commit() {
    asm volatile("cp.async.commit_group;" ::: "memory");
}
template<int N>
__device__ __forceinline__ void cp_wait() {
    asm volatile("cp.async.wait_group %0;" :: "n"(N) : "memory");
}

// ---------------- device scratch (static, allowed) ----------------
__device__ float  g_part_s[512];
__device__ float  g_part_s2[512];
__device__ float  g_stats[2];
__device__ __nv_bfloat16 g_weffh[512*256];          // [idx][feat]; feat: K 0..127, V 128..255
__device__ __nv_bfloat16 g_wqh[64*128];             // fcq_w bf16, [c][f]
__device__ __nv_bfloat16 g_qh[BATCH*HEADS*HW*DK];   // pre-scaled Q, bf16, [bh][q][d]
__device__ __nv_bfloat16 g_kh[BATCH*HEADS*KHW*DK];  // K bf16 [bh][key][d]
__device__ __nv_bfloat16 g_v [BATCH*HEADS*KHW*DK];  // V bf16 [bh][key][d]
__device__ float  g_ctx[BATCH*HW*HD];

// ---------------- launch 0: per-block partial sums (deterministic) ----------------
__global__ void k_part(const float* __restrict__ x)
{
    float s = 0.f, s2 = 0.f;
    int base = blockIdx.x * (NTOT/512);
    for (int i = threadIdx.x; i < NTOT/512; i += 256) {
        float v = x[base + i];
        s  += v;
        s2  = fmaf(v, v, s2);
    }
    #pragma unroll
    for (int off = 16; off; off >>= 1) {
        s  += __shfl_down_sync(0xffffffffu, s,  off);
        s2 += __shfl_down_sync(0xffffffffu, s2, off);
    }
    __shared__ float sh[2][8];
    int lane = threadIdx.x & 31, w = threadIdx.x >> 5;
    if (lane == 0) { sh[0][w] = s; sh[1][w] = s2; }
    __syncthreads();
    if (threadIdx.x == 0) {
        float ts = 0.f, ts2 = 0.f;
        for (int i = 0; i < 8; i++) { ts += sh[0][i]; ts2 += sh[1][i]; }
        g_part_s[blockIdx.x]  = ts;
        g_part_s2[blockIdx.x] = ts2;
    }
}

// ---------------- launch 1: stats (blk 0) + weff fold (blks 1..256) + fcq cvt (blk 257) ----------------
__global__ void k_stats_weff(const float* __restrict__ fck_w, const float* __restrict__ wk,
                             const float* __restrict__ fcv_w, const float* __restrict__ wv,
                             const float* __restrict__ fcq_w)
{
    if (blockIdx.x == 0) {
        __shared__ double sh[512], sh2[512];
        int t = threadIdx.x;
        sh[t]  = (double)g_part_s[t];
        sh2[t] = (double)g_part_s2[t];
        __syncthreads();
        for (int o = 256; o; o >>= 1) {
            if (t < o) { sh[t] += sh[t+o]; sh2[t] += sh2[t+o]; }
            __syncthreads();
        }
        if (t == 0) {
            double n = (double)NTOT;
            double m = sh[0] / n;
            double var = sh2[0] / n - m*m;
            g_stats[0] = (float)m;
            g_stats[1] = (float)rsqrt(var + (double)EPS_LN);
        }
        return;
    }
    if (blockIdx.x == 257) {
        // fcq_w [f][c] f32 -> g_wqh [c][f] bf16
        for (int e = threadIdx.x; e < 8192; e += 512) {
            int c = e >> 7, f = e & 127;
            g_wqh[c*128 + f] = __float2bfloat16(fcq_w[f*64 + c]);
        }
        return;
    }
    int b2 = blockIdx.x - 1;          // 0..255
    int f  = b2 & 127;
    int kv = b2 >> 7;
    const float* fw = kv ? fcv_w : fck_w;
    const float* w8 = kv ? wv    : wk;
    int idx = threadIdx.x;            // 0..511
    float acc = 0.f;
    #pragma unroll 16
    for (int co = 0; co < 64; co++)
        acc = fmaf(__ldg(&fw[f*64+co]), w8[co*512+idx], acc);
    g_weffh[idx*256 + kv*128 + f] = __float2bfloat16(acc);
}

// ---------------- launch 2: tensor-core Q projection + tensor-core KV projection ----------------
// blockIdx.x < 128:  Q-proj GEMM (32 positions)
// blockIdx.x >= 128: KV-proj GEMM (32 positions)
__global__ void __launch_bounds__(128) k_qkv(const float* __restrict__ x,
                    const float* __restrict__ fcq_b,
                    const float* __restrict__ fck_b, const float* __restrict__ fcv_b)
{
    __shared__ __align__(16) char smraw[41984];
    int b   = blockIdx.y;
    int tid = threadIdx.x;
    int l   = tid & 31;
    int pw  = (tid >> 5) & 1;     // position half (16 rows)
    int c0f = 2*(l & 3);
    int lq  = l >> 2;
    const float* xb = x + (size_t)b*C*HW;

    if (blockIdx.x < 128) {
        // ---- Q projection via tensor cores: [32 pos][64 c] x [64 c][128 f] ----
        __nv_bfloat16* xn = (__nv_bfloat16*)smraw;            // [32][72] stride 144B
        __nv_bfloat16* wq = (__nv_bfloat16*)(smraw + 4608);   // [64][136] stride 272B
        int p0 = blockIdx.x * 32;
        float mean = g_stats[0], rstd = g_stats[1];

        for (int e = tid; e < 2048; e += 128) {
            int c = e >> 5, pos = e & 31;
            xn[pos*72 + c] = __float2bfloat16((xb[c*HW + p0 + pos] - mean) * rstd);
        }
        const uint4* wqsrc = (const uint4*)g_wqh;   // 16 uint4 per c-row
        #pragma unroll
        for (int i = 0; i < 8; i++) {
            int e = tid + i*128;
            int r = e >> 4, ch = e & 15;
            *(uint4*)((char*)wq + r*272 + ch*16) = wqsrc[r*16 + ch];
        }
        __syncthreads();

        int fh = tid >> 6;            // feature half: 64 feats each
        const float* bias = fcq_b + fh*64;
        float acc[8][4];
        #pragma unroll
        for (int n = 0; n < 8; n++) {
            float b0 = bias[n*8 + c0f];
            float b1 = bias[n*8 + c0f + 1];
            acc[n][0] = b0; acc[n][1] = b1; acc[n][2] = b0; acc[n][3] = b1;
        }
        uint32_t xq_lane = (uint32_t)__cvta_generic_to_shared(xn)
                         + (uint32_t)((pw*16 + (l & 15))*144 + (l >> 4)*16);
        uint32_t wq_lane = (uint32_t)__cvta_generic_to_shared(wq)
                         + (uint32_t)((l & 15)*272 + (l >> 4)*16 + fh*128);
        #pragma unroll
        for (int kcI = 0; kcI < 4; kcI++) {
            uint32_t a[4];
            ldsm_x4(a[0], a[1], a[2], a[3], xq_lane + kcI*32);
            #pragma unroll
            for (int np = 0; np < 4; np++) {
                uint32_t b0, b1, b2, b3;
                ldsm_x4_t(b0, b1, b2, b3, wq_lane + (uint32_t)(kcI*4352 + np*32));
                mma_bf16(acc[2*np],     a, b0, b1);
                mma_bf16(acc[2*np + 1], a, b2, b3);
            }
        }
        #pragma unroll
        for (int n = 0; n < 8; n++) {
            int f = fh*64 + n*8 + c0f;
            int h = f >> 5, d = f & 31;
            size_t base = ((size_t)(b*HEADS + h)*HW + p0 + pw*16 + lq)*DK + d;
            *(uint32_t*)(g_qh + base)        = bf16x2_of(acc[n][0]*QK_SCALE, acc[n][1]*QK_SCALE);
            *(uint32_t*)(g_qh + base + 8*DK) = bf16x2_of(acc[n][2]*QK_SCALE, acc[n][3]*QK_SCALE);
        }
    } else {
        // ---- KV projection via tensor cores ----
        __nv_bfloat16* gs    = (__nv_bfloat16*)smraw;            // [32][520]
        __nv_bfloat16* wtile = (__nv_bfloat16*)(smraw + 33280);  // [16][264]
        int p0 = (blockIdx.x - 128) * 32;

        // gather: per (pos, ci) compute all 8 taps, one uint4 store
        for (int e = tid; e < 2048; e += 128) {
            int pos = e & 31;
            int ci  = e >> 5;
            int pg = p0 + pos;
            int i = pg >> 5, j = pg & 31;
            int cy = i*2, cx = j*2;
            const float* xc = xb + ci*HW;
            float ctr = xc[cy*WW + cx] * THETA;
            bool top = (i > 0);
            bool lft = (j > 0);
            int up = (cy-1)*WW, md = cy*WW, dn = (cy+1)*WW;
            float t0 = (top && lft) ? xc[up+cx-1] : 0.f;
            float t1 = top ? xc[up+cx]   : 0.f;
            float t2 = top ? xc[up+cx+1] : 0.f;
            float t3 = lft ? xc[md+cx-1] : 0.f;
            float t4 = xc[md+cx+1];
            float t5 = lft ? xc[dn+cx-1] : 0.f;
            float t6 = xc[dn+cx];
            float t7 = xc[dn+cx+1];
            uint4 v;
            v.x = bf16x2_of(t0 - ctr, t1 - ctr);
            v.y = bf16x2_of(t2 - ctr, t3 - ctr);
            v.z = bf16x2_of(t4 - ctr, t5 - ctr);
            v.w = bf16x2_of(t6 - ctr, t7 - ctr);
            *(uint4*)((char*)gs + pos*1040 + ci*16) = v;
        }

        int kv = tid >> 6;            // 0 -> K feats, 1 -> V feats
        const float* bias = kv ? fcv_b : fck_b;

        float acc[16][4];
        #pragma unroll
        for (int n = 0; n < 16; n++) {
            float b0 = bias[n*8 + c0f];
            float b1 = bias[n*8 + c0f + 1];
            acc[n][0] = b0; acc[n][1] = b1; acc[n][2] = b0; acc[n][3] = b1;
        }

        uint32_t gs_lane = (uint32_t)__cvta_generic_to_shared(gs)
                         + (uint32_t)((pw*16 + (l & 15))*1040 + (l >> 4)*16);
        uint32_t wt_lane = (uint32_t)__cvta_generic_to_shared(wtile)
                         + (uint32_t)((l & 15)*528 + (l >> 4)*16 + kv*256);
        const uint4* wsrc = (const uint4*)g_weffh;   // 512B/row = 32 uint4 per idx row

        for (int kc = 0; kc < 512; kc += 16) {
            __syncthreads();
            #pragma unroll
            for (int i = 0; i < 2; i++) {
                int e = tid + i*128;
                int r = e >> 4, c = e & 15;
                *(uint4*)((char*)wtile + r*528 + c*32)      = wsrc[(size_t)(kc + r)*32 + c*2];
                *(uint4*)((char*)wtile + r*528 + c*32 + 16) = wsrc[(size_t)(kc + r)*32 + c*2 + 1];
            }
            __syncthreads();
            uint32_t a[4];
            ldsm_x4(a[0], a[1], a[2], a[3], gs_lane + kc*2);
            #pragma unroll
            for (int np = 0; np < 8; np++) {
                uint32_t b0, b1, b2, b3;
                ldsm_x4_t(b0, b1, b2, b3, wt_lane + (uint32_t)(np*32));
                mma_bf16(acc[2*np],     a, b0, b1);
                mma_bf16(acc[2*np + 1], a, b2, b3);
            }
        }

        __nv_bfloat16* outb = kv ? g_v : g_kh;
        #pragma unroll
        for (int n = 0; n < 16; n++) {
            int f = n*8 + c0f;
            int h = f >> 5, d = f & 31;
            size_t base = ((size_t)(b*HEADS + h)*KHW + p0 + pw*16 + lq)*DK + d;
            *(uint32_t*)(outb + base)        = bf16x2_of(acc[n][0], acc[n][1]);
            *(uint32_t*)(outb + base + 8*DK) = bf16x2_of(acc[n][2], acc[n][3]);
        }
    }
}

// ---------------- launch 3: attention via mma.sync + ldmatrix + cp.async double buffer ----------------
// CTA: 64 q-rows x one (b,h). 4 warps, warp w owns 16 rows. 5 CTAs/SM.
// Single sync + single wait per tile; fill of tile t+1 overlaps compute of tile t.
#define KT 64
#define KBUF 5120    // 64*40*2 bytes per K (or V) buffer
__global__ void __launch_bounds__(128, 5) k_attn(const float* __restrict__ Bmat)
{
    __shared__ __align__(16) __nv_bfloat16 Ksm[2][KT][40];  // stride 80B
    __shared__ __align__(16) __nv_bfloat16 Vsm[2][KT][40];
    int tid = threadIdx.x;
    int w = tid >> 5, l = tid & 31;
    int g = l >> 2, t = l & 3;
    int bh = blockIdx.y, h = bh & 3;
    int q0 = blockIdx.x * 64 + w * 16;

    // Q a-frags (once)
    uint32_t qa[2][4];
    const __nv_bfloat16* Qb = g_qh + ((size_t)bh*HW + q0)*DK;
    #pragma unroll
    for (int kc = 0; kc < 2; kc++) {
        qa[kc][0] = *(const uint32_t*)(Qb + (size_t)g*DK     + kc*16 + 2*t);
        qa[kc][1] = *(const uint32_t*)(Qb + (size_t)(g+8)*DK + kc*16 + 2*t);
        qa[kc][2] = *(const uint32_t*)(Qb + (size_t)g*DK     + kc*16 + 8 + 2*t);
        qa[kc][3] = *(const uint32_t*)(Qb + (size_t)(g+8)*DK + kc*16 + 8 + 2*t);
    }

    float o[4][4];
    float lsum[2];
    lsum[0] = lsum[1] = 0.f;
    #pragma unroll
    for (int db = 0; db < 4; db++)
        o[db][0] = o[db][1] = o[db][2] = o[db][3] = 0.f;

    // ldmatrix lane bases (buffer 0)
    uint32_t ksm0 = (uint32_t)__cvta_generic_to_shared(&Ksm[0][0][0]);
    uint32_t vsm0 = (uint32_t)__cvta_generic_to_shared(&Vsm[0][0][0]);
    uint32_t k_lane = ksm0 + (uint32_t)((l & 7)*80 + (l >> 3)*16);
    uint32_t v_lane = vsm0 + (uint32_t)((l & 15)*80 + (l >> 4)*16);

    // per-thread fill chunk coords: chunks e=tid, tid+128; r=e>>2, c=e&3
    int r0 = tid >> 2,          cc0 = tid & 3;
    int r1 = (tid + 128) >> 2,  cc1 = (tid + 128) & 3;
    uint32_t kd0 = ksm0 + (uint32_t)(r0*80 + cc0*16);
    uint32_t kd1 = ksm0 + (uint32_t)(r1*80 + cc1*16);
    uint32_t vd0 = vsm0 + (uint32_t)(r0*80 + cc0*16);
    uint32_t vd1 = vsm0 + (uint32_t)(r1*80 + cc1*16);

    const float* Bb = Bmat + (size_t)h*HW*KHW;
    const uint4* kg4 = (const uint4*)(g_kh + (size_t)bh*KHW*DK);
    const uint4* vg4 = (const uint4*)(g_v  + (size_t)bh*KHW*DK);

    // prefetch tile 0 into buffer 0
    cp16(kd0, kg4 + (size_t)r0*4 + cc0);
    cp16(kd1, kg4 + (size_t)r1*4 + cc1);
    cp16(vd0, vg4 + (size_t)r0*4 + cc0);
    cp16(vd1, vg4 + (size_t)r1*4 + cc1);
    cp_commit();

    for (int tt = 0; tt < 16; tt++) {
        int c0 = tt * KT;
        uint32_t boff = (uint32_t)((tt & 1) * KBUF);
        cp_wait<0>();
        __syncthreads();
        if (tt < 15) {
            uint32_t nboff = (uint32_t)(((tt + 1) & 1) * KBUF);
            int c1 = c0 + KT;
            cp16(kd0 + nboff, kg4 + (size_t)(c1 + r0)*4 + cc0);
            cp16(kd1 + nboff, kg4 + (size_t)(c1 + r1)*4 + cc1);
            cp16(vd0 + nboff, vg4 + (size_t)(c1 + r0)*4 + cc0);
            cp16(vd1 + nboff, vg4 + (size_t)(c1 + r1)*4 + cc1);
            cp_commit();
        }

        #pragma unroll
        for (int half = 0; half < 2; half++) {
            int c32 = half * 32;
            // ---- S = Q K^T over 32 keys ----
            float s[4][4];
            #pragma unroll
            for (int nb = 0; nb < 4; nb++)
                s[nb][0] = s[nb][1] = s[nb][2] = s[nb][3] = 0.f;
            #pragma unroll
            for (int nb = 0; nb < 4; nb++) {
                uint32_t b0, b1, b2, b3;
                ldsm_x4(b0, b1, b2, b3, k_lane + boff + (uint32_t)((c32 + 8*nb)*80));
                mma_bf16(s[nb], qa[0], b0, b1);
                mma_bf16(s[nb], qa[1], b2, b3);
            }
            // ---- epilogue: +bias, exp, l, pack P ----
            uint32_t pa[2][4];
            #pragma unroll
            for (int nb = 0; nb < 4; nb++) {
                int row = q0 + g;
                size_t bidx = (size_t)row*KHW + c0 + c32 + 8*nb + 2*t;
                float2 bv0 = *(const float2*)(Bb + bidx);
                float2 bv1 = *(const float2*)(Bb + bidx + (size_t)8*KHW);
                float p0 = __expf(s[nb][0] + bv0.x);
                float p1 = __expf(s[nb][1] + bv0.y);
                float p2 = __expf(s[nb][2] + bv1.x);
                float p3 = __expf(s[nb][3] + bv1.y);
                lsum[0] += (p0 + p1);
                lsum[1] += (p2 + p3);
                int u = nb >> 1, odd = nb & 1;
                pa[u][2*odd]     = bf16x2_of(p0, p1);
                pa[u][2*odd + 1] = bf16x2_of(p2, p3);
            }
            // ---- O += P V (trans ldmatrix from [key][dim]) ----
            #pragma unroll
            for (int u = 0; u < 2; u++)
                #pragma unroll
                for (int dp = 0; dp < 2; dp++) {
                    uint32_t b0, b1, b2, b3;
                    ldsm_x4_t(b0, b1, b2, b3,
                              v_lane + boff + (uint32_t)((c32 + 16*u)*80 + dp*32));
                    mma_bf16(o[2*dp],     pa[u], b0, b1);
                    mma_bf16(o[2*dp + 1], pa[u], b2, b3);
                }
        }
        __syncthreads();
    }

    // reduce l over the t-quad, normalize, store ctx
    #pragma unroll
    for (int r = 0; r < 2; r++) {
        float v = lsum[r];
        v += __shfl_xor_sync(0xffffffffu, v, 1);
        v += __shfl_xor_sync(0xffffffffu, v, 2);
        lsum[r] = 1.f / v;
    }
    int b = bh >> 2;
    int row = q0 + g;
    #pragma unroll
    for (int db = 0; db < 4; db++) {
        int dim = h*DK + 8*db + 2*t;
        float2 lo = make_float2(o[db][0]*lsum[0], o[db][1]*lsum[0]);
        float2 hi = make_float2(o[db][2]*lsum[1], o[db][3]*lsum[1]);
        *(float2*)(g_ctx + ((size_t)b*HW + row)*HD + dim)     = lo;
        *(float2*)(g_ctx + ((size_t)b*HW + row + 8)*HD + dim) = hi;
    }
}

// ---------------- launch 4: output projection + residual, f32x2 packed ----------------
__global__ void k_out(const float* __restrict__ x,
                      const float* __restrict__ fco_w,
                      const float* __restrict__ fco_b,
                      float* __restrict__ out)
{
    __shared__ float cs[16*128];
    __shared__ float ws2[64*130];
    int b   = blockIdx.y;
    int p0  = blockIdx.x * 16;
    int tid = threadIdx.x;

    for (int e = tid; e < 8192; e += 256) {
        int ch = e >> 7, k = e & 127;
        ws2[ch*130+k] = fco_w[e];
    }
    const float* ctx = g_ctx + ((size_t)b*HW + p0)*HD;
    for (int e = tid; e < 2048; e += 256) cs[e] = ctx[e];
    __syncthreads();

    int ch = tid & 63;
    int pg = tid >> 6;
    ull acc2[4];
    #pragma unroll
    for (int pi = 0; pi < 4; pi++) acc2[pi] = 0ull;
    const ull* wr = (const ull*)(ws2 + ch*130);
    #pragma unroll 4
    for (int kp = 0; kp < 64; kp++) {
        ull w2 = wr[kp];
        #pragma unroll
        for (int pi = 0; pi < 4; pi++) {
            ull c2 = *(const ull*)(cs + (pg*4+pi)*128 + 2*kp);
            fma2(acc2[pi], w2, c2, acc2[pi]);
        }
    }
    float bias = fco_b[ch];
    #pragma unroll
    for (int pi = 0; pi < 4; pi++) {
        float a0, a1; unpack2(a0, a1, acc2[pi]);
        int pos = pg*4 + pi;
        size_t oi = (size_t)b*(C*HW) + (size_t)(p0+pos)*64 + ch;
        out[oi] = (a0 + a1) + bias + x[oi];
    }
}

// ---------------- launcher (5 launches; k_attn is launch idx 3) ----------------
extern "C" void kernel_launch(void* const* d_in, const int* in_sizes, int n_in,
                              void* d_out, int out_size)
{
    (void)n_in; (void)out_size; (void)in_sizes;
    const float* x      = (const float*)d_in[0];
    const float* wk     = (const float*)d_in[1];
    const float* wv     = (const float*)d_in[2];
    const float* fcq_w  = (const float*)d_in[3];
    const float* fcq_b  = (const float*)d_in[4];
    const float* fck_w  = (const float*)d_in[5];
    const float* fck_b  = (const float*)d_in[6];
    const float* fcv_w  = (const float*)d_in[7];
    const float* fcv_b  = (const float*)d_in[8];
    const float* fco_w  = (const float*)d_in[9];
    const float* fco_b  = (const float*)d_in[10];
    const float* Bmat   = (const float*)d_in[11];
    float* out = (float*)d_out;

    k_part<<<512, 256>>>(x);
    k_stats_weff<<<258, 512>>>(fck_w, wk, fcv_w, wv, fcq_w);
    k_qkv<<<dim3(128+32, BATCH), 128>>>(x, fcq_b, fck_b, fcv_b);
    k_attn<<<dim3(HW/64, BATCH*HEADS), 128>>>(Bmat);
    k_out<<<dim3(HW/16, BATCH), 256>>>(x, fco_w, fco_b, out);
}

// round 17
// speedup vs baseline: 1.7637x; 1.1535x over previous
#include <cuda_runtime.h>
#include <cuda_bf16.h>
#include <math.h>
#include <stdint.h>

// ---------------- problem constants (fixed shapes) ----------------
#define BATCH 8
#define C     64
#define HH    64
#define WW    64
#define HW    4096          // 64*64
#define HEADS 4
#define DK    32
#define HD    128           // HEADS*DK
#define KHW   1024          // 32*32 (stride-2 output)
#define THETA 0.5f
#define EPS_LN 1e-5f
#define NTOT  (BATCH*C*HW)  // 2097152
#define QK_SCALE 0.17677669529663687f
#define LOG2E    1.4426950408889634f
#define QSCL     (QK_SCALE * LOG2E)     // folded: exp(x) = exp2(x*log2e)

typedef unsigned long long ull;

__device__ __forceinline__ uint32_t bf16x2_of(float a, float b) {
    uint32_t r;
    asm("cvt.rn.satfinite.bf16x2.f32 %0, %1, %2;" : "=r"(r) : "f"(b), "f"(a));
    return r;   // lo=a, hi=b
}
__device__ __forceinline__ float ex2(float x) {
    float r; asm("ex2.approx.ftz.f32 %0, %1;" : "=f"(r) : "f"(x)); return r;
}

// warp mma: D(16x8,f32) += A(16x16,bf16,row) * B(16x8,bf16,col)
__device__ __forceinline__ void mma_bf16(float* d, const uint32_t* a,
                                         uint32_t b0, uint32_t b1) {
    asm volatile("mma.sync.aligned.m16n8k16.row.col.f32.bf16.bf16.f32 "
        "{%0,%1,%2,%3}, {%4,%5,%6,%7}, {%8,%9}, {%0,%1,%2,%3};"
        : "+f"(d[0]), "+f"(d[1]), "+f"(d[2]), "+f"(d[3])
        : "r"(a[0]), "r"(a[1]), "r"(a[2]), "r"(a[3]), "r"(b0), "r"(b1));
}
__device__ __forceinline__ void ldsm_x4(uint32_t& r0, uint32_t& r1,
                                        uint32_t& r2, uint32_t& r3, uint32_t addr) {
    asm volatile("ldmatrix.sync.aligned.m8n8.x4.shared.b16 {%0,%1,%2,%3}, [%4];"
        : "=r"(r0), "=r"(r1), "=r"(r2), "=r"(r3) : "r"(addr));
}
__device__ __forceinline__ void ldsm_x4_t(uint32_t& r0, uint32_t& r1,
                                          uint32_t& r2, uint32_t& r3, uint32_t addr) {
    asm volatile("ldmatrix.sync.aligned.m8n8.x4.trans.shared.b16 {%0,%1,%2,%3}, [%4];"
        : "=r"(r0), "=r"(r1), "=r"(r2), "=r"(r3) : "r"(addr));
}
__device__ __forceinline__ void cp16(uint32_t smem_dst, const void* gsrc) {
    asm volatile("cp.async.cg.shared.global [%0], [%1], 16;"
                 :: "r"(smem_dst), "l"(gsrc) : "memory");
}
__device__ __forceinline__ void cp_commit() {
    asm volatile("cp.async.commit_group;" ::: "memory");
}
template<int N>
__device__ __forceinline__ void cp_wait() {
    asm volatile("cp.async.wait_group %0;" :: "n"(N) : "memory");
}

// ---------------- device scratch (static, allowed) ----------------
__device__ float  g_part_s[512];
__device__ float  g_part_s2[512];
__device__ float  g_stats[2];
__device__ __nv_bfloat16 g_weffh[512*256];          // [idx][feat]; K 0..127, V 128..255
__device__ __nv_bfloat16 g_wqh[64*128];             // fcq_w bf16, [c][f]
__device__ __nv_bfloat16 g_woh[128*64];             // fco_w bf16, [k][ch]
__device__ __nv_bfloat16 g_qh[BATCH*HEADS*HW*DK];   // Q*(QK_SCALE*log2e), bf16, [bh][q][d]
__device__ __nv_bfloat16 g_kh[BATCH*HEADS*KHW*DK];  // K bf16 [bh][key][d]
__device__ __nv_bfloat16 g_v [BATCH*HEADS*KHW*DK];  // V bf16 [bh][key][d]
__device__ __nv_bfloat16 g_ctxh[BATCH*HW*HD];       // ctx bf16 [b][pos][128]

// ---------------- launch 0: per-block partial sums (deterministic) ----------------
__global__ void k_part(const float* __restrict__ x)
{
    float s = 0.f, s2 = 0.f;
    int base = blockIdx.x * (NTOT/512);
    for (int i = threadIdx.x; i < NTOT/512; i += 256) {
        float v = x[base + i];
        s  += v;
        s2  = fmaf(v, v, s2);
    }
    #pragma unroll
    for (int off = 16; off; off >>= 1) {
        s  += __shfl_down_sync(0xffffffffu, s,  off);
        s2 += __shfl_down_sync(0xffffffffu, s2, off);
    }
    __shared__ float sh[2][8];
    int lane = threadIdx.x & 31, w = threadIdx.x >> 5;
    if (lane == 0) { sh[0][w] = s; sh[1][w] = s2; }
    __syncthreads();
    if (threadIdx.x == 0) {
        float ts = 0.f, ts2 = 0.f;
        for (int i = 0; i < 8; i++) { ts += sh[0][i]; ts2 += sh[1][i]; }
        g_part_s[blockIdx.x]  = ts;
        g_part_s2[blockIdx.x] = ts2;
    }
}

// ---------------- launch 1: stats + weight preps ----------------
// blk 0: stats; blks 1..256: weff fold; blk 257: fcq cvt; blk 258: fco transpose cvt
__global__ void k_stats_weff(const float* __restrict__ fck_w, const float* __restrict__ wk,
                             const float* __restrict__ fcv_w, const float* __restrict__ wv,
                             const float* __restrict__ fcq_w, const float* __restrict__ fco_w)
{
    if (blockIdx.x == 0) {
        __shared__ double sh[512], sh2[512];
        int t = threadIdx.x;
        sh[t]  = (double)g_part_s[t];
        sh2[t] = (double)g_part_s2[t];
        __syncthreads();
        for (int o = 256; o; o >>= 1) {
            if (t < o) { sh[t] += sh[t+o]; sh2[t] += sh2[t+o]; }
            __syncthreads();
        }
        if (t == 0) {
            double n = (double)NTOT;
            double m = sh[0] / n;
            double var = sh2[0] / n - m*m;
            g_stats[0] = (float)m;
            g_stats[1] = (float)rsqrt(var + (double)EPS_LN);
        }
        return;
    }
    if (blockIdx.x == 257) {
        for (int e = threadIdx.x; e < 8192; e += 512) {
            int c = e >> 7, f = e & 127;
            g_wqh[c*128 + f] = __float2bfloat16(fcq_w[f*64 + c]);
        }
        return;
    }
    if (blockIdx.x == 258) {
        // fco_w [ch][k] f32 -> g_woh [k][ch] bf16
        for (int e = threadIdx.x; e < 8192; e += 512) {
            int k = e >> 6, ch = e & 63;
            g_woh[k*64 + ch] = __float2bfloat16(fco_w[ch*128 + k]);
        }
        return;
    }
    int b2 = blockIdx.x - 1;          // 0..255
    int f  = b2 & 127;
    int kv = b2 >> 7;
    const float* fw = kv ? fcv_w : fck_w;
    const float* w8 = kv ? wv    : wk;
    int idx = threadIdx.x;            // 0..511
    float acc = 0.f;
    #pragma unroll 16
    for (int co = 0; co < 64; co++)
        acc = fmaf(__ldg(&fw[f*64+co]), w8[co*512+idx], acc);
    g_weffh[idx*256 + kv*128 + f] = __float2bfloat16(acc);
}

// ---------------- launch 2: tensor-core Q projection + tensor-core KV projection ----------------
__global__ void __launch_bounds__(128) k_qkv(const float* __restrict__ x,
                    const float* __restrict__ fcq_b,
                    const float* __restrict__ fck_b, const float* __restrict__ fcv_b)
{
    __shared__ __align__(16) char smraw[41984];
    int b   = blockIdx.y;
    int tid = threadIdx.x;
    int l   = tid & 31;
    int pw  = (tid >> 5) & 1;
    int c0f = 2*(l & 3);
    int lq  = l >> 2;
    const float* xb = x + (size_t)b*C*HW;

    if (blockIdx.x < 128) {
        // ---- Q projection ----
        __nv_bfloat16* xn = (__nv_bfloat16*)smraw;            // [32][72] stride 144B
        __nv_bfloat16* wq = (__nv_bfloat16*)(smraw + 4608);   // [64][136] stride 272B
        int p0 = blockIdx.x * 32;
        float mean = g_stats[0], rstd = g_stats[1];

        for (int e = tid; e < 2048; e += 128) {
            int c = e >> 5, pos = e & 31;
            xn[pos*72 + c] = __float2bfloat16((xb[c*HW + p0 + pos] - mean) * rstd);
        }
        const uint4* wqsrc = (const uint4*)g_wqh;
        #pragma unroll
        for (int i = 0; i < 8; i++) {
            int e = tid + i*128;
            int r = e >> 4, ch = e & 15;
            *(uint4*)((char*)wq + r*272 + ch*16) = wqsrc[r*16 + ch];
        }
        __syncthreads();

        int fh = tid >> 6;
        const float* bias = fcq_b + fh*64;
        float acc[8][4];
        #pragma unroll
        for (int n = 0; n < 8; n++) {
            float b0 = bias[n*8 + c0f];
            float b1 = bias[n*8 + c0f + 1];
            acc[n][0] = b0; acc[n][1] = b1; acc[n][2] = b0; acc[n][3] = b1;
        }
        uint32_t xq_lane = (uint32_t)__cvta_generic_to_shared(xn)
                         + (uint32_t)((pw*16 + (l & 15))*144 + (l >> 4)*16);
        uint32_t wq_lane = (uint32_t)__cvta_generic_to_shared(wq)
                         + (uint32_t)((l & 15)*272 + (l >> 4)*16 + fh*128);
        #pragma unroll
        for (int kcI = 0; kcI < 4; kcI++) {
            uint32_t a[4];
            ldsm_x4(a[0], a[1], a[2], a[3], xq_lane + kcI*32);
            #pragma unroll
            for (int np = 0; np < 4; np++) {
                uint32_t b0, b1, b2, b3;
                ldsm_x4_t(b0, b1, b2, b3, wq_lane + (uint32_t)(kcI*4352 + np*32));
                mma_bf16(acc[2*np],     a, b0, b1);
                mma_bf16(acc[2*np + 1], a, b2, b3);
            }
        }
        #pragma unroll
        for (int n = 0; n < 8; n++) {
            int f = fh*64 + n*8 + c0f;
            int h = f >> 5, d = f & 31;
            size_t base = ((size_t)(b*HEADS + h)*HW + p0 + pw*16 + lq)*DK + d;
            *(uint32_t*)(g_qh + base)        = bf16x2_of(acc[n][0]*QSCL, acc[n][1]*QSCL);
            *(uint32_t*)(g_qh + base + 8*DK) = bf16x2_of(acc[n][2]*QSCL, acc[n][3]*QSCL);
        }
    } else {
        // ---- KV projection ----
        __nv_bfloat16* gs    = (__nv_bfloat16*)smraw;            // [32][520]
        __nv_bfloat16* wtile = (__nv_bfloat16*)(smraw + 33280);  // [16][264]
        int p0 = (blockIdx.x - 128) * 32;

        for (int e = tid; e < 2048; e += 128) {
            int pos = e & 31;
            int ci  = e >> 5;
            int pg = p0 + pos;
            int i = pg >> 5, j = pg & 31;
            int cy = i*2, cx = j*2;
            const float* xc = xb + ci*HW;
            float ctr = xc[cy*WW + cx] * THETA;
            bool top = (i > 0);
            bool lft = (j > 0);
            int up = (cy-1)*WW, md = cy*WW, dn = (cy+1)*WW;
            float t0 = (top && lft) ? xc[up+cx-1] : 0.f;
            float t1 = top ? xc[up+cx]   : 0.f;
            float t2 = top ? xc[up+cx+1] : 0.f;
            float t3 = lft ? xc[md+cx-1] : 0.f;
            float t4 = xc[md+cx+1];
            float t5 = lft ? xc[dn+cx-1] : 0.f;
            float t6 = xc[dn+cx];
            float t7 = xc[dn+cx+1];
            uint4 v;
            v.x = bf16x2_of(t0 - ctr, t1 - ctr);
            v.y = bf16x2_of(t2 - ctr, t3 - ctr);
            v.z = bf16x2_of(t4 - ctr, t5 - ctr);
            v.w = bf16x2_of(t6 - ctr, t7 - ctr);
            *(uint4*)((char*)gs + pos*1040 + ci*16) = v;
        }

        int kv = tid >> 6;
        const float* bias = kv ? fcv_b : fck_b;
        float acc[16][4];
        #pragma unroll
        for (int n = 0; n < 16; n++) {
            float b0 = bias[n*8 + c0f];
            float b1 = bias[n*8 + c0f + 1];
            acc[n][0] = b0; acc[n][1] = b1; acc[n][2] = b0; acc[n][3] = b1;
        }

        uint32_t gs_lane = (uint32_t)__cvta_generic_to_shared(gs)
                         + (uint32_t)((pw*16 + (l & 15))*1040 + (l >> 4)*16);
        uint32_t wt_lane = (uint32_t)__cvta_generic_to_shared(wtile)
                         + (uint32_t)((l & 15)*528 + (l >> 4)*16 + kv*256);
        const uint4* wsrc = (const uint4*)g_weffh;   // 32 uint4 per idx row

        for (int kc = 0; kc < 512; kc += 16) {
            __syncthreads();
            #pragma unroll
            for (int i = 0; i < 2; i++) {
                int e = tid + i*128;
                int r = e >> 4, c = e & 15;
                *(uint4*)((char*)wtile + r*528 + c*32)      = wsrc[(size_t)(kc + r)*32 + c*2];
                *(uint4*)((char*)wtile + r*528 + c*32 + 16) = wsrc[(size_t)(kc + r)*32 + c*2 + 1];
            }
            __syncthreads();
            uint32_t a[4];
            ldsm_x4(a[0], a[1], a[2], a[3], gs_lane + kc*2);
            #pragma unroll
            for (int np = 0; np < 8; np++) {
                uint32_t b0, b1, b2, b3;
                ldsm_x4_t(b0, b1, b2, b3, wt_lane + (uint32_t)(np*32));
                mma_bf16(acc[2*np],     a, b0, b1);
                mma_bf16(acc[2*np + 1], a, b2, b3);
            }
        }

        __nv_bfloat16* outb = kv ? g_v : g_kh;
        #pragma unroll
        for (int n = 0; n < 16; n++) {
            int f = n*8 + c0f;
            int h = f >> 5, d = f & 31;
            size_t base = ((size_t)(b*HEADS + h)*KHW + p0 + pw*16 + lq)*DK + d;
            *(uint32_t*)(outb + base)        = bf16x2_of(acc[n][0], acc[n][1]);
            *(uint32_t*)(outb + base + 8*DK) = bf16x2_of(acc[n][2], acc[n][3]);
        }
    }
}

// ---------------- launch 3: attention (mma.sync + ldmatrix + cp.async, exp2 domain) ----------------
#define KT 64
#define KBUF 5120
__global__ void __launch_bounds__(128, 5) k_attn(const float* __restrict__ Bmat)
{
    __shared__ __align__(16) __nv_bfloat16 Ksm[2][KT][40];
    __shared__ __align__(16) __nv_bfloat16 Vsm[2][KT][40];
    int tid = threadIdx.x;
    int w = tid >> 5, l = tid & 31;
    int g = l >> 2, t = l & 3;
    int bh = blockIdx.y, h = bh & 3;
    int q0 = blockIdx.x * 64 + w * 16;

    uint32_t qa[2][4];
    const __nv_bfloat16* Qb = g_qh + ((size_t)bh*HW + q0)*DK;
    #pragma unroll
    for (int kc = 0; kc < 2; kc++) {
        qa[kc][0] = *(const uint32_t*)(Qb + (size_t)g*DK     + kc*16 + 2*t);
        qa[kc][1] = *(const uint32_t*)(Qb + (size_t)(g+8)*DK + kc*16 + 2*t);
        qa[kc][2] = *(const uint32_t*)(Qb + (size_t)g*DK     + kc*16 + 8 + 2*t);
        qa[kc][3] = *(const uint32_t*)(Qb + (size_t)(g+8)*DK + kc*16 + 8 + 2*t);
    }

    float o[4][4];
    float lsum[2];
    lsum[0] = lsum[1] = 0.f;
    #pragma unroll
    for (int db = 0; db < 4; db++)
        o[db][0] = o[db][1] = o[db][2] = o[db][3] = 0.f;

    uint32_t ksm0 = (uint32_t)__cvta_generic_to_shared(&Ksm[0][0][0]);
    uint32_t vsm0 = (uint32_t)__cvta_generic_to_shared(&Vsm[0][0][0]);
    uint32_t k_lane = ksm0 + (uint32_t)((l & 7)*80 + (l >> 3)*16);
    uint32_t v_lane = vsm0 + (uint32_t)((l & 15)*80 + (l >> 4)*16);

    int r0 = tid >> 2,          cc0 = tid & 3;
    int r1 = (tid + 128) >> 2,  cc1 = (tid + 128) & 3;
    uint32_t kd0 = ksm0 + (uint32_t)(r0*80 + cc0*16);
    uint32_t kd1 = ksm0 + (uint32_t)(r1*80 + cc1*16);
    uint32_t vd0 = vsm0 + (uint32_t)(r0*80 + cc0*16);
    uint32_t vd1 = vsm0 + (uint32_t)(r1*80 + cc1*16);

    const float* Bb = Bmat + (size_t)h*HW*KHW;
    const uint4* kg4 = (const uint4*)(g_kh + (size_t)bh*KHW*DK);
    const uint4* vg4 = (const uint4*)(g_v  + (size_t)bh*KHW*DK);

    cp16(kd0, kg4 + (size_t)r0*4 + cc0);
    cp16(kd1, kg4 + (size_t)r1*4 + cc1);
    cp16(vd0, vg4 + (size_t)r0*4 + cc0);
    cp16(vd1, vg4 + (size_t)r1*4 + cc1);
    cp_commit();

    for (int tt = 0; tt < 16; tt++) {
        int c0 = tt * KT;
        uint32_t boff = (uint32_t)((tt & 1) * KBUF);
        cp_wait<0>();
        __syncthreads();
        if (tt < 15) {
            uint32_t nboff = (uint32_t)(((tt + 1) & 1) * KBUF);
            int c1 = c0 + KT;
            cp16(kd0 + nboff, kg4 + (size_t)(c1 + r0)*4 + cc0);
            cp16(kd1 + nboff, kg4 + (size_t)(c1 + r1)*4 + cc1);
            cp16(vd0 + nboff, vg4 + (size_t)(c1 + r0)*4 + cc0);
            cp16(vd1 + nboff, vg4 + (size_t)(c1 + r1)*4 + cc1);
            cp_commit();
        }

        #pragma unroll
        for (int half = 0; half < 2; half++) {
            int c32 = half * 32;
            float s[4][4];
            #pragma unroll
            for (int nb = 0; nb < 4; nb++)
                s[nb][0] = s[nb][1] = s[nb][2] = s[nb][3] = 0.f;
            #pragma unroll
            for (int nb = 0; nb < 4; nb++) {
                uint32_t b0, b1, b2, b3;
                ldsm_x4(b0, b1, b2, b3, k_lane + boff + (uint32_t)((c32 + 8*nb)*80));
                mma_bf16(s[nb], qa[0], b0, b1);
                mma_bf16(s[nb], qa[1], b2, b3);
            }
            uint32_t pa[2][4];
            #pragma unroll
            for (int nb = 0; nb < 4; nb++) {
                int row = q0 + g;
                size_t bidx = (size_t)row*KHW + c0 + c32 + 8*nb + 2*t;
                float2 bv0 = *(const float2*)(Bb + bidx);
                float2 bv1 = *(const float2*)(Bb + bidx + (size_t)8*KHW);
                float p0 = ex2(fmaf(bv0.x, LOG2E, s[nb][0]));
                float p1 = ex2(fmaf(bv0.y, LOG2E, s[nb][1]));
                float p2 = ex2(fmaf(bv1.x, LOG2E, s[nb][2]));
                float p3 = ex2(fmaf(bv1.y, LOG2E, s[nb][3]));
                lsum[0] += (p0 + p1);
                lsum[1] += (p2 + p3);
                int u = nb >> 1, odd = nb & 1;
                pa[u][2*odd]     = bf16x2_of(p0, p1);
                pa[u][2*odd + 1] = bf16x2_of(p2, p3);
            }
            #pragma unroll
            for (int u = 0; u < 2; u++)
                #pragma unroll
                for (int dp = 0; dp < 2; dp++) {
                    uint32_t b0, b1, b2, b3;
                    ldsm_x4_t(b0, b1, b2, b3,
                              v_lane + boff + (uint32_t)((c32 + 16*u)*80 + dp*32));
                    mma_bf16(o[2*dp],     pa[u], b0, b1);
                    mma_bf16(o[2*dp + 1], pa[u], b2, b3);
                }
        }
        __syncthreads();
    }

    #pragma unroll
    for (int r = 0; r < 2; r++) {
        float v = lsum[r];
        v += __shfl_xor_sync(0xffffffffu, v, 1);
        v += __shfl_xor_sync(0xffffffffu, v, 2);
        lsum[r] = 1.f / v;
    }
    int b = bh >> 2;
    int row = q0 + g;
    #pragma unroll
    for (int db = 0; db < 4; db++) {
        int dim = h*DK + 8*db + 2*t;
        *(uint32_t*)(g_ctxh + ((size_t)b*HW + row)*HD + dim) =
            bf16x2_of(o[db][0]*lsum[0], o[db][1]*lsum[0]);
        *(uint32_t*)(g_ctxh + ((size_t)b*HW + row + 8)*HD + dim) =
            bf16x2_of(o[db][2]*lsum[1], o[db][3]*lsum[1]);
    }
}

// ---------------- launch 4: output projection via tensor cores + bias + residual ----------------
// CTA = 32 positions x one batch; grid (HW/32, BATCH). ctx[32][128]bf16 @ woh[128][64] -> [32][64]
__global__ void __launch_bounds__(128) k_out(const float* __restrict__ x,
                                             const float* __restrict__ fco_b,
                                             float* __restrict__ out)
{
    __shared__ __align__(16) char smraw[27136];
    __nv_bfloat16* cs = (__nv_bfloat16*)smraw;            // [32][136] stride 272B
    __nv_bfloat16* wo = (__nv_bfloat16*)(smraw + 8704);   // [128][72] stride 144B
    int b   = blockIdx.y;
    int p0  = blockIdx.x * 32;
    int tid = threadIdx.x;
    int l   = tid & 31;
    int pw  = (tid >> 5) & 1;
    int fh  = tid >> 6;
    int g   = l >> 2;
    int c0f = 2*(l & 3);

    // stage ctx tile (bf16 already): 512 uint4 chunks
    const uint4* ctx4 = (const uint4*)(g_ctxh + ((size_t)b*HW + p0)*HD);
    #pragma unroll
    for (int i = 0; i < 4; i++) {
        int e = tid + i*128;
        int r = e >> 4, c = e & 15;
        *(uint4*)((char*)cs + r*272 + c*16) = ctx4[r*16 + c];
    }
    // stage wo tile: 1024 uint4 chunks? g_woh 128 rows x 64 ch = 128B = 8 uint4 per row
    const uint4* wo4 = (const uint4*)g_woh;
    #pragma unroll
    for (int i = 0; i < 8; i++) {
        int e = tid + i*128;
        int r = e >> 3, c = e & 7;
        *(uint4*)((char*)wo + r*144 + c*16) = wo4[r*8 + c];
    }
    __syncthreads();

    float acc[4][4];
    #pragma unroll
    for (int n = 0; n < 4; n++)
        acc[n][0] = acc[n][1] = acc[n][2] = acc[n][3] = 0.f;

    uint32_t a_lane = (uint32_t)__cvta_generic_to_shared(cs)
                    + (uint32_t)((pw*16 + (l & 15))*272 + (l >> 4)*16);
    uint32_t w_lane = (uint32_t)__cvta_generic_to_shared(wo)
                    + (uint32_t)((l & 15)*144 + (l >> 4)*16 + fh*64);
    #pragma unroll
    for (int kc = 0; kc < 8; kc++) {
        uint32_t a[4];
        ldsm_x4(a[0], a[1], a[2], a[3], a_lane + kc*32);
        #pragma unroll
        for (int np = 0; np < 2; np++) {
            uint32_t b0, b1, b2, b3;
            ldsm_x4_t(b0, b1, b2, b3, w_lane + (uint32_t)(kc*2304 + np*32));
            mma_bf16(acc[2*np],     a, b0, b1);
            mma_bf16(acc[2*np + 1], a, b2, b3);
        }
    }

    int rowb = p0 + pw*16 + g;
    #pragma unroll
    for (int n = 0; n < 4; n++) {
        int ch = fh*32 + n*8 + c0f;
        float2 bb = *(const float2*)(fco_b + ch);
        size_t oi0 = (size_t)b*(C*HW) + (size_t)rowb*64 + ch;
        size_t oi1 = oi0 + 8*64;
        float2 x0 = *(const float2*)(x + oi0);
        float2 x1 = *(const float2*)(x + oi1);
        *(float2*)(out + oi0) = make_float2(acc[n][0] + bb.x + x0.x,
                                            acc[n][1] + bb.y + x0.y);
        *(float2*)(out + oi1) = make_float2(acc[n][2] + bb.x + x1.x,
                                            acc[n][3] + bb.y + x1.y);
    }
}

// ---------------- launcher (5 launches; k_attn is launch idx 3) ----------------
extern "C" void kernel_launch(void* const* d_in, const int* in_sizes, int n_in,
                              void* d_out, int out_size)
{
    (void)n_in; (void)out_size; (void)in_sizes;
    const float* x      = (const float*)d_in[0];
    const float* wk     = (const float*)d_in[1];
    const float* wv     = (const float*)d_in[2];
    const float* fcq_w  = (const float*)d_in[3];
    const float* fcq_b  = (const float*)d_in[4];
    const float* fck_w  = (const float*)d_in[5];
    const float* fck_b  = (const float*)d_in[6];
    const float* fcv_w  = (const float*)d_in[7];
    const float* fcv_b  = (const float*)d_in[8];
    const float* fco_w  = (const float*)d_in[9];
    const float* fco_b  = (const float*)d_in[10];
    const float* Bmat   = (const float*)d_in[11];
    float* out = (float*)d_out;

    k_part<<<512, 256>>>(x);
    k_stats_weff<<<259, 512>>>(fck_w, wk, fcv_w, wv, fcq_w, fco_w);
    k_qkv<<<dim3(128+32, BATCH), 128>>>(x, fcq_b, fck_b, fcv_b);
    k_attn<<<dim3(HW/64, BATCH*HEADS), 128>>>(Bmat);
    k_out<<<dim3(HW/32, BATCH), 128>>>(x, fco_b, out);
}